// round 5
// baseline (speedup 1.0000x reference)
#include <cuda_runtime.h>
#include <cstdint>
#include <cstddef>

// Problem constants (fixed by setup_inputs)
#define kB 64
#define kN 4096
#define kS 8
#define kD 256
#define kM 1024
#define kNITER 3

// ---------------- scratch (static device globals; no allocation) ----------------
__device__ float g_slots_buf[512 * 256];
__device__ float g_lnbuf[512 * 256];
__device__ float g_qbuf[512 * 256];
__device__ float g_qkbuf[512 * 256];
__device__ float g_Ubuf[512 * 256];
__device__ float g_rowsum[512];
__device__ float g_upd[512 * 256];
__device__ float g_gi[512 * 768];
__device__ float g_gh[512 * 768];
__device__ float g_hbuf[512 * 1024];

// ---------------- LayerNorm over rows of length 256 ----------------
__global__ void ln_rows_k(const float* __restrict__ X, const float* __restrict__ g,
                          const float* __restrict__ b, float* __restrict__ Y) {
    int row = blockIdx.x;
    int t = threadIdx.x;
    float x = X[(size_t)row * 256 + t];
    float s1 = x, s2 = x * x;
#pragma unroll
    for (int off = 16; off; off >>= 1) {
        s1 += __shfl_xor_sync(~0u, s1, off);
        s2 += __shfl_xor_sync(~0u, s2, off);
    }
    __shared__ float w1[8], w2[8];
    int wid = t >> 5, lane = t & 31;
    if (lane == 0) { w1[wid] = s1; w2[wid] = s2; }
    __syncthreads();
    if (wid == 0) {
        float a = (lane < 8) ? w1[lane] : 0.f;
        float c = (lane < 8) ? w2[lane] : 0.f;
#pragma unroll
        for (int off = 4; off; off >>= 1) {
            a += __shfl_xor_sync(~0u, a, off);
            c += __shfl_xor_sync(~0u, c, off);
        }
        if (lane == 0) { w1[0] = a; w2[0] = c; }
    }
    __syncthreads();
    float mu = w1[0] * (1.f / 256.f);
    float var = w2[0] * (1.f / 256.f) - mu * mu;
    float rstd = rsqrtf(var + 1e-5f);
    Y[(size_t)row * 256 + t] = (x - mu) * rstd * g[t] + b[t];
}

// ---------------- generic fp32 tiled GEMM: C = A @ op(B) (+epilogue) ----------------
// bTrans=1: B is [N,K] (C = A @ B^T).  bTrans=0: B is [K,N] (C = A @ B).
// Epilogue order: (1/rowden[m]) -> +bias[n] -> relu -> +resid[m,n]
// TM=64, TN=64, 256 threads, 16x16 thread grid, each thread 4x4 accumulators.
__global__ void __launch_bounds__(256) gemm_k(
    const float* __restrict__ A, const float* __restrict__ Bm, float* __restrict__ C,
    int M, int N, int K, int bTrans,
    const float* __restrict__ bias, const float* __restrict__ rowden,
    const float* __restrict__ resid, int relu)
{
    constexpr int TM = 64, TN = 64, TK = 16;
    constexpr int RM = 4, RN = 4;
    __shared__ float As[TK][TM + 1];
    __shared__ __align__(16) float Bs[TK][TN + 8];
    int tid = threadIdx.x;
    int tx = tid & 15, ty = tid >> 4;
    int m0 = blockIdx.x * TM, n0 = blockIdx.y * TN;

    float acc[RM][RN];
#pragma unroll
    for (int i = 0; i < RM; i++)
#pragma unroll
        for (int j = 0; j < RN; j++) acc[i][j] = 0.f;

    for (int k0 = 0; k0 < K; k0 += TK) {
        // A tile: 64 rows x 16 k, one float4 per thread, stored transposed
        {
            int r = tid >> 2, q = tid & 3;
            float4 v = *(const float4*)(A + (size_t)(m0 + r) * K + k0 + 4 * q);
            As[4 * q + 0][r] = v.x; As[4 * q + 1][r] = v.y;
            As[4 * q + 2][r] = v.z; As[4 * q + 3][r] = v.w;
        }
        if (bTrans) {
            int r = tid >> 2, q = tid & 3;
            float4 v = *(const float4*)(Bm + (size_t)(n0 + r) * K + k0 + 4 * q);
            Bs[4 * q + 0][r] = v.x; Bs[4 * q + 1][r] = v.y;
            Bs[4 * q + 2][r] = v.z; Bs[4 * q + 3][r] = v.w;
        } else {
            int r = tid >> 4, q = tid & 15;  // 16 rows x 16 col-groups of 4
            float4 v = *(const float4*)(Bm + (size_t)(k0 + r) * N + n0 + 4 * q);
            *(float4*)&Bs[r][4 * q] = v;
        }
        __syncthreads();
#pragma unroll
        for (int kk = 0; kk < TK; kk++) {
            float a[RM];
#pragma unroll
            for (int i = 0; i < RM; i++) a[i] = As[kk][ty * RM + i];
            float4 bv = *(const float4*)&Bs[kk][tx * 4];
            float bb[4] = {bv.x, bv.y, bv.z, bv.w};
#pragma unroll
            for (int i = 0; i < RM; i++)
#pragma unroll
                for (int j = 0; j < RN; j++)
                    acc[i][j] = fmaf(a[i], bb[j], acc[i][j]);
        }
        __syncthreads();
    }
#pragma unroll
    for (int i = 0; i < RM; i++) {
        int m = m0 + ty * RM + i;
        float rsf = rowden ? __fdividef(1.f, rowden[m]) : 1.f;
#pragma unroll
        for (int j = 0; j < RN; j++) {
            int n = n0 + tx * RN + j;
            float v = acc[i][j];
            if (rowden) v *= rsf;
            if (bias) v += bias[n];
            if (relu) v = fmaxf(v, 0.f);
            if (resid) v += resid[(size_t)m * N + n];
            C[(size_t)m * N + n] = v;
        }
    }
}

// ---------------- fused: per (b,n) LN -> logits -> softmax(slots) -> attn + U/rowsum ----------------
// qk: [B,S,D] = (LN(slots)@Wq^T)@Wk.  Writes attn [B,S,N] and accumulates
// U[b,i,e] = sum_n attn[b,i,n]*LN(f)[b,n,e],  rowsum[b,i] = sum_n attn[b,i,n].
__global__ void __launch_bounds__(256, 1) attn_fused_k(
    const float* __restrict__ features,
    const float* __restrict__ qk,
    const float* __restrict__ gfeat, const float* __restrict__ bfeat,
    float* __restrict__ attn_out, float* __restrict__ U, float* __restrict__ rowsum)
{
    __shared__ float attn_s[8][256];
    __shared__ float Us[8][256];
    __shared__ float rs_s[8];
    int tid = threadIdx.x;
    int lane = tid & 31, wid = tid >> 5;
    int b = blockIdx.y;
    int nbase = blockIdx.x * 256;

#pragma unroll
    for (int i = 0; i < 8; i++) Us[i][tid] = 0.f;
    if (tid < 8) rs_s[tid] = 0.f;

    // lane owns elements e = lane + 32*j
    float qkr[8][8], gr[8], br[8];
#pragma unroll
    for (int j = 0; j < 8; j++) {
        gr[j] = gfeat[lane + 32 * j];
        br[j] = bfeat[lane + 32 * j];
    }
#pragma unroll
    for (int i = 0; i < 8; i++)
#pragma unroll
        for (int j = 0; j < 8; j++)
            qkr[i][j] = qk[((size_t)(b * 8 + i) << 8) + lane + 32 * j];
    __syncthreads();

    float u[8][8];
    float rs[8];
#pragma unroll
    for (int i = 0; i < 8; i++) {
        rs[i] = 0.f;
#pragma unroll
        for (int j = 0; j < 8; j++) u[i][j] = 0.f;
    }

    const int n0 = nbase + wid * 32;
    const float* fp = features + ((size_t)b * kN + n0) * 256 + lane;

    float cur[8], nxt[8];
#pragma unroll
    for (int j = 0; j < 8; j++) cur[j] = fp[32 * j];

    for (int r = 0; r < 32; r++) {
        if (r < 31) {
            const float* fpn = fp + (size_t)(r + 1) * 256;
#pragma unroll
            for (int j = 0; j < 8; j++) nxt[j] = fpn[32 * j];
        }
        // LayerNorm stats
        float s1 = 0.f, s2 = 0.f;
#pragma unroll
        for (int j = 0; j < 8; j++) { s1 += cur[j]; s2 = fmaf(cur[j], cur[j], s2); }
#pragma unroll
        for (int off = 16; off; off >>= 1) {
            s1 += __shfl_xor_sync(~0u, s1, off);
            s2 += __shfl_xor_sync(~0u, s2, off);
        }
        float mu = s1 * (1.f / 256.f);
        float var = fmaf(-mu, mu, s2 * (1.f / 256.f));
        float rstd = rsqrtf(var + 1e-5f);
        float fln[8];
#pragma unroll
        for (int j = 0; j < 8; j++) fln[j] = fmaf((cur[j] - mu) * rstd, gr[j], br[j]);

        // 8 slot logits (dot over D)
        float d[8];
#pragma unroll
        for (int i = 0; i < 8; i++) {
            float s = 0.f;
#pragma unroll
            for (int j = 0; j < 8; j++) s = fmaf(qkr[i][j], fln[j], s);
            d[i] = s;
        }
#pragma unroll
        for (int i = 0; i < 8; i++)
#pragma unroll
            for (int off = 16; off; off >>= 1) d[i] += __shfl_xor_sync(~0u, d[i], off);

        // softmax over slots (scale = D^-0.5 = 1/16), + epsilon
        float mx = d[0];
#pragma unroll
        for (int i = 1; i < 8; i++) mx = fmaxf(mx, d[i]);
        float e[8], sum = 0.f;
#pragma unroll
        for (int i = 0; i < 8; i++) { e[i] = __expf(0.0625f * (d[i] - mx)); sum += e[i]; }
        float inv = __fdividef(1.f, sum);
        float a[8];
#pragma unroll
        for (int i = 0; i < 8; i++) { a[i] = fmaf(e[i], inv, 1e-8f); rs[i] += a[i]; }

        // accumulate U
#pragma unroll
        for (int i = 0; i < 8; i++)
#pragma unroll
            for (int j = 0; j < 8; j++) u[i][j] = fmaf(a[i], fln[j], u[i][j]);

        if (lane == 0) {
#pragma unroll
            for (int i = 0; i < 8; i++) attn_s[i][wid * 32 + r] = a[i];
        }
#pragma unroll
        for (int j = 0; j < 8; j++) cur[j] = nxt[j];
    }

    // per-warp -> block reduction (conflict-free: addr = lane + 32j)
#pragma unroll
    for (int i = 0; i < 8; i++)
#pragma unroll
        for (int j = 0; j < 8; j++)
            atomicAdd(&Us[i][lane + 32 * j], u[i][j]);
    if (lane == 0) {
#pragma unroll
        for (int i = 0; i < 8; i++) atomicAdd(&rs_s[i], rs[i]);
    }
    __syncthreads();

    // coalesced global writes
#pragma unroll
    for (int i = 0; i < 8; i++)
        attn_out[(size_t)(b * 8 + i) * 4096 + nbase + tid] = attn_s[i][tid];
#pragma unroll
    for (int i = 0; i < 8; i++)
        atomicAdd(&U[((size_t)(b * 8 + i) << 8) + tid], Us[i][tid]);
    if (tid < 8) atomicAdd(&rowsum[b * 8 + tid], rs_s[tid]);
}

// ---------------- GRU cell elementwise (in-place on slots) ----------------
__global__ void gru_k(const float* __restrict__ gi, const float* __restrict__ gh,
                      float* __restrict__ slots)
{
    int idx = blockIdx.x * blockDim.x + threadIdx.x;  // 512*256
    int row = idx >> 8, col = idx & 255;
    size_t base = (size_t)row * 768 + col;
    float ir = gi[base], iz = gi[base + 256], in_ = gi[base + 512];
    float hr = gh[base], hz = gh[base + 256], hn = gh[base + 512];
    float r = 1.f / (1.f + __expf(-(ir + hr)));
    float z = 1.f / (1.f + __expf(-(iz + hz)));
    float nn = tanhf(fmaf(r, hn, in_));
    float h = slots[idx];
    slots[idx] = fmaf(z, h - nn, nn);  // (1-z)*n + z*h
}

// ---------------- launcher ----------------
extern "C" void kernel_launch(void* const* d_in, const int* in_sizes, int n_in,
                              void* d_out, int out_size)
{
    const float* features   = (const float*)d_in[0];
    const float* slots_init = (const float*)d_in[1];
    const float* g_feat     = (const float*)d_in[2];
    const float* b_feat     = (const float*)d_in[3];
    const float* g_slots    = (const float*)d_in[4];
    const float* b_slots    = (const float*)d_in[5];
    const float* g_mlp      = (const float*)d_in[6];
    const float* b_mlp      = (const float*)d_in[7];
    const float* Wk         = (const float*)d_in[8];
    const float* Wv         = (const float*)d_in[9];
    const float* Wq         = (const float*)d_in[10];
    const float* w_ih       = (const float*)d_in[11];
    const float* w_hh       = (const float*)d_in[12];
    const float* b_ih       = (const float*)d_in[13];
    const float* b_hh       = (const float*)d_in[14];
    const float* W1         = (const float*)d_in[15];
    const float* b1         = (const float*)d_in[16];
    const float* W2         = (const float*)d_in[17];
    const float* b2         = (const float*)d_in[18];

    float* out       = (float*)d_out;
    float* out_slots = out;                         // [64,8,256]
    float* out_attn  = out + (size_t)64 * 8 * 256;  // [64,8,4096]

    float *slots, *lnbuf, *qbuf, *qkbuf, *U, *rowsum, *upd, *gi, *gh, *hbuf;
    cudaGetSymbolAddress((void**)&slots, g_slots_buf);
    cudaGetSymbolAddress((void**)&lnbuf, g_lnbuf);
    cudaGetSymbolAddress((void**)&qbuf, g_qbuf);
    cudaGetSymbolAddress((void**)&qkbuf, g_qkbuf);
    cudaGetSymbolAddress((void**)&U, g_Ubuf);
    cudaGetSymbolAddress((void**)&rowsum, g_rowsum);
    cudaGetSymbolAddress((void**)&upd, g_upd);
    cudaGetSymbolAddress((void**)&gi, g_gi);
    cudaGetSymbolAddress((void**)&gh, g_gh);
    cudaGetSymbolAddress((void**)&hbuf, g_hbuf);

    cudaMemcpyAsync(slots, slots_init, (size_t)512 * 256 * 4,
                    cudaMemcpyDeviceToDevice, 0);

    for (int it = 0; it < kNITER; it++) {
        // q = LN(slots) @ Wq^T ; qk = q @ Wk
        ln_rows_k<<<512, 256>>>(slots, g_slots, b_slots, lnbuf);
        gemm_k<<<dim3(8, 4), 256>>>(lnbuf, Wq, qbuf, 512, 256, 256, 1,
                                    nullptr, nullptr, nullptr, 0);
        gemm_k<<<dim3(8, 4), 256>>>(qbuf, Wk, qkbuf, 512, 256, 256, 0,
                                    nullptr, nullptr, nullptr, 0);
        cudaMemsetAsync(U, 0, (size_t)512 * 256 * 4, 0);
        cudaMemsetAsync(rowsum, 0, (size_t)512 * 4, 0);
        // fused big pass over features
        attn_fused_k<<<dim3(16, 64), 256>>>(features, qkbuf, g_feat, b_feat,
                                            out_attn, U, rowsum);
        // updates = (U @ Wv^T) / rowsum
        gemm_k<<<dim3(8, 4), 256>>>(U, Wv, upd, 512, 256, 256, 1,
                                    nullptr, rowsum, nullptr, 0);
        // GRU gates
        gemm_k<<<dim3(8, 12), 256>>>(upd, w_ih, gi, 512, 768, 256, 1,
                                     b_ih, nullptr, nullptr, 0);
        gemm_k<<<dim3(8, 12), 256>>>(slots, w_hh, gh, 512, 768, 256, 1,
                                     b_hh, nullptr, nullptr, 0);
        gru_k<<<512, 256>>>(gi, gh, slots);
        // MLP with residual
        ln_rows_k<<<512, 256>>>(slots, g_mlp, b_mlp, lnbuf);
        gemm_k<<<dim3(8, 16), 256>>>(lnbuf, W1, hbuf, 512, 1024, 256, 1,
                                     b1, nullptr, nullptr, 1);
        gemm_k<<<dim3(8, 4), 256>>>(hbuf, W2, slots, 512, 256, 1024, 1,
                                    b2, nullptr, slots, 0);
    }
    cudaMemcpyAsync(out_slots, slots, (size_t)512 * 256 * 4,
                    cudaMemcpyDeviceToDevice, 0);
}

// round 6
// speedup vs baseline: 1.5840x; 1.5840x over previous
#include <cuda_runtime.h>
#include <cstdint>
#include <cstddef>

// Problem constants (fixed by setup_inputs)
#define kB 64
#define kN 4096
#define kS 8
#define kD 256
#define kM 1024
#define kNITER 3

typedef unsigned long long u64;

// ---------------- f32x2 packed math helpers (Blackwell FFMA2) ----------------
__device__ __forceinline__ u64 pk2(float lo, float hi) {
    u64 r;
    asm("mov.b64 %0, {%1,%2};" : "=l"(r)
        : "r"(__float_as_uint(lo)), "r"(__float_as_uint(hi)));
    return r;
}
__device__ __forceinline__ void upk2(u64 v, float& lo, float& hi) {
    unsigned a, b;
    asm("mov.b64 {%0,%1}, %2;" : "=r"(a), "=r"(b) : "l"(v));
    lo = __uint_as_float(a); hi = __uint_as_float(b);
}
__device__ __forceinline__ u64 fma2_(u64 a, u64 b, u64 c) {
    u64 d;
    asm("fma.rn.f32x2 %0, %1, %2, %3;" : "=l"(d) : "l"(a), "l"(b), "l"(c));
    return d;
}

// ---------------- scratch (static device globals; no allocation) ----------------
__device__ float g_slots_buf[512 * 256];
__device__ float2 g_st[512];                 // per-row (mu, rstd)
__device__ float g_qkbuf[512 * 256];
__device__ float g_Ubuf[512 * 256];
__device__ float g_rowsum[512];
__device__ float g_gi[512 * 768];
__device__ float g_gh[512 * 768];
__device__ float g_hbuf[512 * 1024];
__device__ float g_Wqk[256 * 256];           // Wq^T @ Wk
__device__ float g_Wvih[768 * 256];          // w_ih @ Wv

// ---------------- per-row LN stats (rows of length 256) ----------------
__global__ void stats_k(const float* __restrict__ X, float2* __restrict__ st) {
    int row = blockIdx.x * 8 + (threadIdx.x >> 5);
    int lane = threadIdx.x & 31;
    const float* xp = X + (size_t)row * 256 + lane;
    float s1 = 0.f, s2 = 0.f;
#pragma unroll
    for (int j = 0; j < 8; j++) { float x = xp[32 * j]; s1 += x; s2 = fmaf(x, x, s2); }
#pragma unroll
    for (int o = 16; o; o >>= 1) {
        s1 += __shfl_xor_sync(~0u, s1, o);
        s2 += __shfl_xor_sync(~0u, s2, o);
    }
    if (lane == 0) {
        float mu = s1 * (1.f / 256.f);
        float var = fmaf(-mu, mu, s2 * (1.f / 256.f));
        st[row] = make_float2(mu, rsqrtf(var + 1e-5f));
    }
}

// ---------------- fp32 tiled GEMM with fused LN-on-A, rowden, bias, relu, atomic split-K ----------------
// bTrans=1: C = A @ B^T (B [N,K]); bTrans=0: C = A @ B (B [K,N]).
// If lnst: A element a -> (a - mu)*rstd*lng[k] + lnb[k].
// K range per block: [z*kLen, (z+1)*kLen). atomicOut: atomicAdd into C (bias only at z==0).
__global__ void __launch_bounds__(256) gemm_k(
    const float* __restrict__ A, const float* __restrict__ Bm, float* __restrict__ C,
    int M, int N, int K, int kLen, int bTrans,
    const float* __restrict__ bias, const float* __restrict__ rowden,
    const float2* __restrict__ lnst, const float* __restrict__ lng,
    const float* __restrict__ lnb, int relu, int atomicOut)
{
    constexpr int TM = 64, TN = 64, TK = 16;
    __shared__ float As[TK][TM + 4];
    __shared__ __align__(16) float Bs[TK][TN + 8];
    int tid = threadIdx.x;
    int tx = tid & 15, ty = tid >> 4;
    int m0 = blockIdx.x * TM, n0 = blockIdx.y * TN;
    int kbeg = blockIdx.z * kLen, kend = kbeg + kLen;
    int ra = tid >> 2, qa = tid & 3;

    float2 stv = make_float2(0.f, 1.f);
    if (lnst) stv = lnst[m0 + ra];

    u64 acc[4][2];
#pragma unroll
    for (int i = 0; i < 4; i++) { acc[i][0] = 0ull; acc[i][1] = 0ull; }

    for (int k0 = kbeg; k0 < kend; k0 += TK) {
        float4 v = *(const float4*)(A + (size_t)(m0 + ra) * K + k0 + 4 * qa);
        if (lnst) {
            float4 g4 = *(const float4*)(lng + k0 + 4 * qa);
            float4 b4 = *(const float4*)(lnb + k0 + 4 * qa);
            v.x = fmaf((v.x - stv.x) * stv.y, g4.x, b4.x);
            v.y = fmaf((v.y - stv.x) * stv.y, g4.y, b4.y);
            v.z = fmaf((v.z - stv.x) * stv.y, g4.z, b4.z);
            v.w = fmaf((v.w - stv.x) * stv.y, g4.w, b4.w);
        }
        As[4 * qa + 0][ra] = v.x; As[4 * qa + 1][ra] = v.y;
        As[4 * qa + 2][ra] = v.z; As[4 * qa + 3][ra] = v.w;
        if (bTrans) {
            float4 w = *(const float4*)(Bm + (size_t)(n0 + ra) * K + k0 + 4 * qa);
            Bs[4 * qa + 0][ra] = w.x; Bs[4 * qa + 1][ra] = w.y;
            Bs[4 * qa + 2][ra] = w.z; Bs[4 * qa + 3][ra] = w.w;
        } else {
            int rb = tid >> 4, qb = tid & 15;
            float4 w = *(const float4*)(Bm + (size_t)(k0 + rb) * N + n0 + 4 * qb);
            *(float4*)&Bs[rb][4 * qb] = w;
        }
        __syncthreads();
#pragma unroll
        for (int kk = 0; kk < TK; kk++) {
            float4 bv = *(const float4*)&Bs[kk][tx * 4];
            u64 b0 = pk2(bv.x, bv.y), b1 = pk2(bv.z, bv.w);
#pragma unroll
            for (int i = 0; i < 4; i++) {
                float a = As[kk][ty * 4 + i];
                u64 a2 = pk2(a, a);
                acc[i][0] = fma2_(a2, b0, acc[i][0]);
                acc[i][1] = fma2_(a2, b1, acc[i][1]);
            }
        }
        __syncthreads();
    }
#pragma unroll
    for (int i = 0; i < 4; i++) {
        int m = m0 + ty * 4 + i;
        float rsf = rowden ? __fdividef(1.f, rowden[m]) : 1.f;
        float c[4];
        upk2(acc[i][0], c[0], c[1]);
        upk2(acc[i][1], c[2], c[3]);
#pragma unroll
        for (int j = 0; j < 4; j++) {
            int n = n0 + tx * 4 + j;
            float vv = c[j];
            if (rowden) vv *= rsf;
            if (bias && blockIdx.z == 0) vv += bias[n];
            if (relu) vv = fmaxf(vv, 0.f);
            if (atomicOut) atomicAdd(&C[(size_t)m * N + n], vv);
            else C[(size_t)m * N + n] = vv;
        }
    }
}

// ---------------- C = A^T @ B  (A:[K,M], B:[K,N], both row-major) ----------------
__global__ void __launch_bounds__(256) gemm_tn_k(
    const float* __restrict__ A, const float* __restrict__ Bm, float* __restrict__ C,
    int M, int N, int K)
{
    constexpr int TM = 64, TN = 64, TK = 16;
    __shared__ __align__(16) float As[TK][TM + 8];
    __shared__ __align__(16) float Bs[TK][TN + 8];
    int tid = threadIdx.x;
    int tx = tid & 15, ty = tid >> 4;
    int m0 = blockIdx.x * TM, n0 = blockIdx.y * TN;

    u64 acc[4][2];
#pragma unroll
    for (int i = 0; i < 4; i++) { acc[i][0] = 0ull; acc[i][1] = 0ull; }

    for (int k0 = 0; k0 < K; k0 += TK) {
        int r = tid >> 4, q = tid & 15;
        *(float4*)&As[r][4 * q] = *(const float4*)(A + (size_t)(k0 + r) * M + m0 + 4 * q);
        *(float4*)&Bs[r][4 * q] = *(const float4*)(Bm + (size_t)(k0 + r) * N + n0 + 4 * q);
        __syncthreads();
#pragma unroll
        for (int kk = 0; kk < TK; kk++) {
            float4 bv = *(const float4*)&Bs[kk][tx * 4];
            u64 b0 = pk2(bv.x, bv.y), b1 = pk2(bv.z, bv.w);
#pragma unroll
            for (int i = 0; i < 4; i++) {
                float a = As[kk][ty * 4 + i];
                u64 a2 = pk2(a, a);
                acc[i][0] = fma2_(a2, b0, acc[i][0]);
                acc[i][1] = fma2_(a2, b1, acc[i][1]);
            }
        }
        __syncthreads();
    }
#pragma unroll
    for (int i = 0; i < 4; i++) {
        int m = m0 + ty * 4 + i;
        float c[4];
        upk2(acc[i][0], c[0], c[1]);
        upk2(acc[i][1], c[2], c[3]);
#pragma unroll
        for (int j = 0; j < 4; j++)
            C[(size_t)m * N + n0 + tx * 4 + j] = c[j];
    }
}

// ---------------- fused attention pass ----------------
// Per block: 128 n-rows of batch b, processed in 4 tiles of 32 rows.
// Phases per tile: P1 LN->smem; P2 dots (warp = 4 slots x 8 rows); P3 softmax
// (warp 0, thread=row) + attn STG; P4 U accumulate (f32x2).
__global__ void __launch_bounds__(256, 2) attn_fused_k(
    const float* __restrict__ features, const float* __restrict__ qk,
    const float* __restrict__ gfeat, const float* __restrict__ bfeat,
    float* __restrict__ attn_out, float* __restrict__ U, float* __restrict__ rowsum)
{
    __shared__ float fs[32][257];
    __shared__ float ds[32][9];
    __shared__ float as_[8][33];
    int tid = threadIdx.x, lane = tid & 31, w = tid >> 5;
    int b = blockIdx.y;
    int n0 = blockIdx.x * 128;
    int sg = w & 1, rg = w >> 1;

    float gr[8], br[8];
#pragma unroll
    for (int j = 0; j < 8; j++) { gr[j] = gfeat[lane + 32 * j]; br[j] = bfeat[lane + 32 * j]; }

    u64 qkr2[4][4];
#pragma unroll
    for (int i = 0; i < 4; i++) {
        const float* qp = qk + ((size_t)(b * 8 + 4 * sg + i) << 8) + lane;
#pragma unroll
        for (int jj = 0; jj < 4; jj++)
            qkr2[i][jj] = pk2(qp[64 * jj], qp[64 * jj + 32]);
    }

    u64 u2[4][4];
#pragma unroll
    for (int i = 0; i < 4; i++)
#pragma unroll
        for (int jj = 0; jj < 4; jj++) u2[i][jj] = 0ull;
    float rs_acc[8];
#pragma unroll
    for (int i = 0; i < 8; i++) rs_acc[i] = 0.f;

    for (int t = 0; t < 4; t++) {
        // ---- P1: LayerNorm rows 4w..4w+3 of this tile into fs ----
        const float* fp = features + ((size_t)b * kN + n0 + t * 32 + 4 * w) * 256 + lane;
#pragma unroll
        for (int rr = 0; rr < 4; rr++) {
            float x[8];
#pragma unroll
            for (int j = 0; j < 8; j++) x[j] = fp[(size_t)rr * 256 + 32 * j];
            float s1 = 0.f, s2 = 0.f;
#pragma unroll
            for (int j = 0; j < 8; j++) { s1 += x[j]; s2 = fmaf(x[j], x[j], s2); }
#pragma unroll
            for (int o = 16; o; o >>= 1) {
                s1 += __shfl_xor_sync(~0u, s1, o);
                s2 += __shfl_xor_sync(~0u, s2, o);
            }
            float mu = s1 * (1.f / 256.f);
            float var = fmaf(-mu, mu, s2 * (1.f / 256.f));
            float rstd = rsqrtf(var + 1e-5f);
#pragma unroll
            for (int j = 0; j < 8; j++)
                fs[4 * w + rr][lane + 32 * j] = fmaf((x[j] - mu) * rstd, gr[j], br[j]);
        }
        __syncthreads();
        // ---- P2: logits for slots 4sg..4sg+3, rows 8rg..8rg+7 ----
#pragma unroll
        for (int rr = 0; rr < 8; rr++) {
            int row = 8 * rg + rr;
            u64 f2[4];
#pragma unroll
            for (int jj = 0; jj < 4; jj++)
                f2[jj] = pk2(fs[row][lane + 64 * jj], fs[row][lane + 64 * jj + 32]);
#pragma unroll
            for (int i = 0; i < 4; i++) {
                u64 d2 = 0ull;
#pragma unroll
                for (int jj = 0; jj < 4; jj++) d2 = fma2_(qkr2[i][jj], f2[jj], d2);
                float lo, hi; upk2(d2, lo, hi);
                float d = lo + hi;
#pragma unroll
                for (int o = 16; o; o >>= 1) d += __shfl_xor_sync(~0u, d, o);
                if (lane == 0) ds[row][4 * sg + i] = d;
            }
        }
        __syncthreads();
        // ---- P3: softmax over slots (warp 0, thread = row) ----
        if (w == 0) {
            float dd[8];
#pragma unroll
            for (int i = 0; i < 8; i++) dd[i] = ds[lane][i];
            float mx = dd[0];
#pragma unroll
            for (int i = 1; i < 8; i++) mx = fmaxf(mx, dd[i]);
            float e[8], sum = 0.f;
#pragma unroll
            for (int i = 0; i < 8; i++) { e[i] = __expf(0.0625f * (dd[i] - mx)); sum += e[i]; }
            float inv = __fdividef(1.f, sum);
#pragma unroll
            for (int i = 0; i < 8; i++) {
                float a = fmaf(e[i], inv, 1e-8f);
                rs_acc[i] += a;
                as_[i][lane] = a;
                attn_out[(size_t)(b * 8 + i) * 4096 + n0 + t * 32 + lane] = a;
            }
        }
        __syncthreads();
        // ---- P4: U accumulation (f32x2) ----
#pragma unroll
        for (int rr = 0; rr < 8; rr++) {
            int row = 8 * rg + rr;
            u64 f2[4];
#pragma unroll
            for (int jj = 0; jj < 4; jj++)
                f2[jj] = pk2(fs[row][lane + 64 * jj], fs[row][lane + 64 * jj + 32]);
#pragma unroll
            for (int i = 0; i < 4; i++) {
                float a = as_[4 * sg + i][row];
                u64 a2 = pk2(a, a);
#pragma unroll
                for (int jj = 0; jj < 4; jj++) u2[i][jj] = fma2_(a2, f2[jj], u2[i][jj]);
            }
        }
        __syncthreads();
    }

    // ---- block-level U reduction via smem (reuse fs), then global atomics ----
    float* fsU = &fs[0][0];   // first 8*257 floats
#pragma unroll
    for (int i = 0; i < 8; i++) fsU[i * 257 + tid] = 0.f;
    __syncthreads();
#pragma unroll
    for (int i = 0; i < 4; i++)
#pragma unroll
        for (int jj = 0; jj < 4; jj++) {
            float lo, hi; upk2(u2[i][jj], lo, hi);
            atomicAdd(&fsU[(4 * sg + i) * 257 + lane + 64 * jj], lo);
            atomicAdd(&fsU[(4 * sg + i) * 257 + lane + 64 * jj + 32], hi);
        }
    __syncthreads();
#pragma unroll
    for (int i = 0; i < 8; i++)
        atomicAdd(&U[((size_t)(b * 8 + i) << 8) + tid], fsU[i * 257 + tid]);
    if (w == 0) {
#pragma unroll
        for (int i = 0; i < 8; i++) {
            float v = rs_acc[i];
#pragma unroll
            for (int o = 16; o; o >>= 1) v += __shfl_xor_sync(~0u, v, o);
            if (lane == 0) atomicAdd(&rowsum[b * 8 + i], v);
        }
    }
}

// ---------------- GRU cell + next-LN stats (block = one slot row) ----------------
__global__ void gru_stats_k(const float* __restrict__ gi, const float* __restrict__ gh,
                            float* __restrict__ slots, float2* __restrict__ st)
{
    int row = blockIdx.x, c = threadIdx.x;
    size_t base = (size_t)row * 768 + c;
    float ir = gi[base], iz = gi[base + 256], in_ = gi[base + 512];
    float hr = gh[base], hz = gh[base + 256], hn = gh[base + 512];
    float r = 1.f / (1.f + __expf(-(ir + hr)));
    float z = 1.f / (1.f + __expf(-(iz + hz)));
    float nn = tanhf(fmaf(r, hn, in_));
    float h = slots[(size_t)row * 256 + c];
    float v = fmaf(z, h - nn, nn);
    slots[(size_t)row * 256 + c] = v;

    float s1 = v, s2 = v * v;
#pragma unroll
    for (int o = 16; o; o >>= 1) {
        s1 += __shfl_xor_sync(~0u, s1, o);
        s2 += __shfl_xor_sync(~0u, s2, o);
    }
    __shared__ float w1[8], w2[8];
    int wid = c >> 5, lane = c & 31;
    if (lane == 0) { w1[wid] = s1; w2[wid] = s2; }
    __syncthreads();
    if (c == 0) {
        float a = 0.f, b = 0.f;
#pragma unroll
        for (int i = 0; i < 8; i++) { a += w1[i]; b += w2[i]; }
        float mu = a * (1.f / 256.f);
        float var = fmaf(-mu, mu, b * (1.f / 256.f));
        st[row] = make_float2(mu, rsqrtf(var + 1e-5f));
    }
}

// ---------------- launcher ----------------
extern "C" void kernel_launch(void* const* d_in, const int* in_sizes, int n_in,
                              void* d_out, int out_size)
{
    const float* features   = (const float*)d_in[0];
    const float* slots_init = (const float*)d_in[1];
    const float* g_feat     = (const float*)d_in[2];
    const float* b_feat     = (const float*)d_in[3];
    const float* g_slots    = (const float*)d_in[4];
    const float* b_slots    = (const float*)d_in[5];
    const float* g_mlp      = (const float*)d_in[6];
    const float* b_mlp      = (const float*)d_in[7];
    const float* Wk         = (const float*)d_in[8];
    const float* Wv         = (const float*)d_in[9];
    const float* Wq         = (const float*)d_in[10];
    const float* w_ih       = (const float*)d_in[11];
    const float* w_hh       = (const float*)d_in[12];
    const float* b_ih       = (const float*)d_in[13];
    const float* b_hh       = (const float*)d_in[14];
    const float* W1         = (const float*)d_in[15];
    const float* b1         = (const float*)d_in[16];
    const float* W2         = (const float*)d_in[17];
    const float* b2         = (const float*)d_in[18];

    float* out       = (float*)d_out;
    float* out_slots = out;                         // [64,8,256]
    float* out_attn  = out + (size_t)64 * 8 * 256;  // [64,8,4096]

    float *slots, *qkbuf, *U, *rowsum, *gi, *gh, *hbuf, *Wqk, *Wvih;
    float2* st;
    cudaGetSymbolAddress((void**)&slots, g_slots_buf);
    cudaGetSymbolAddress((void**)&st, g_st);
    cudaGetSymbolAddress((void**)&qkbuf, g_qkbuf);
    cudaGetSymbolAddress((void**)&U, g_Ubuf);
    cudaGetSymbolAddress((void**)&rowsum, g_rowsum);
    cudaGetSymbolAddress((void**)&gi, g_gi);
    cudaGetSymbolAddress((void**)&gh, g_gh);
    cudaGetSymbolAddress((void**)&hbuf, g_hbuf);
    cudaGetSymbolAddress((void**)&Wqk, g_Wqk);
    cudaGetSymbolAddress((void**)&Wvih, g_Wvih);

    // Precompute folded weights: Wqk = Wq^T @ Wk ; Wvih = w_ih @ Wv
    gemm_tn_k<<<dim3(4, 4), 256>>>(Wq, Wk, Wqk, 256, 256, 256);
    gemm_k<<<dim3(12, 4), 256>>>(w_ih, Wv, Wvih, 768, 256, 256, 256, 0,
                                 nullptr, nullptr, nullptr, nullptr, nullptr, 0, 0);

    cudaMemcpyAsync(slots, slots_init, (size_t)512 * 256 * 4,
                    cudaMemcpyDeviceToDevice, 0);

    for (int it = 0; it < kNITER; it++) {
        // LN stats of slots, then qk = LN(slots) @ Wqk
        stats_k<<<64, 256>>>(slots, st);
        gemm_k<<<dim3(8, 4), 256>>>(slots, Wqk, qkbuf, 512, 256, 256, 256, 0,
                                    nullptr, nullptr, st, g_slots, b_slots, 0, 0);
        cudaMemsetAsync(U, 0, (size_t)512 * 256 * 4, 0);
        cudaMemsetAsync(rowsum, 0, (size_t)512 * 4, 0);
        // fused big pass over features
        attn_fused_k<<<dim3(32, 64), 256>>>(features, qkbuf, g_feat, b_feat,
                                            out_attn, U, rowsum);
        // gi = (U @ Wvih^T)/rowsum + b_ih   (upd GEMM folded away)
        gemm_k<<<dim3(8, 12), 256>>>(U, Wvih, gi, 512, 768, 256, 256, 1,
                                     b_ih, rowsum, nullptr, nullptr, nullptr, 0, 0);
        // gh = slots @ w_hh^T + b_hh
        gemm_k<<<dim3(8, 12), 256>>>(slots, w_hh, gh, 512, 768, 256, 256, 1,
                                     b_hh, nullptr, nullptr, nullptr, nullptr, 0, 0);
        // GRU + LN stats for MLP
        gru_stats_k<<<512, 256>>>(gi, gh, slots, st);
        // h = relu(LN(slots) @ W1^T + b1)
        gemm_k<<<dim3(8, 16), 256>>>(slots, W1, hbuf, 512, 1024, 256, 256, 1,
                                     b1, nullptr, st, g_mlp, b_mlp, 1, 0);
        // slots += h @ W2^T + b2   (split-K=4, atomic accumulate in place)
        gemm_k<<<dim3(8, 4, 4), 256>>>(hbuf, W2, slots, 512, 256, 1024, 256, 1,
                                       b2, nullptr, nullptr, nullptr, nullptr, 0, 1);
    }
    cudaMemcpyAsync(out_slots, slots, (size_t)512 * 256 * 4,
                    cudaMemcpyDeviceToDevice, 0);
}

// round 7
// speedup vs baseline: 1.7845x; 1.1266x over previous
#include <cuda_runtime.h>
#include <cstdint>
#include <cstddef>

// Problem constants (fixed by setup_inputs)
#define kB 64
#define kN 4096
#define kS 8
#define kD 256
#define kM 1024
#define kNITER 3

typedef unsigned long long u64;

// ---------------- f32x2 packed math helpers (Blackwell FFMA2) ----------------
__device__ __forceinline__ u64 pk2(float lo, float hi) {
    u64 r;
    asm("mov.b64 %0, {%1,%2};" : "=l"(r)
        : "r"(__float_as_uint(lo)), "r"(__float_as_uint(hi)));
    return r;
}
__device__ __forceinline__ void upk2(u64 v, float& lo, float& hi) {
    unsigned a, b;
    asm("mov.b64 {%0,%1}, %2;" : "=r"(a), "=r"(b) : "l"(v));
    lo = __uint_as_float(a); hi = __uint_as_float(b);
}
__device__ __forceinline__ u64 fma2_(u64 a, u64 b, u64 c) {
    u64 d;
    asm("fma.rn.f32x2 %0, %1, %2, %3;" : "=l"(d) : "l"(a), "l"(b), "l"(c));
    return d;
}

// ---------------- scratch (static device globals; no allocation) ----------------
__device__ float g_slots_buf[512 * 256];
__device__ float g_qkbuf[512 * 256];
__device__ float g_Ubuf[512 * 256];
__device__ float g_rowsum[512];
__device__ float g_gi[512 * 768];
__device__ float g_gh[512 * 768];
__device__ float g_hbuf[512 * 1024];
__device__ float g_Wqk[256 * 256];     // Wq^T @ Wk (raw)
__device__ float g_Bcat[256 * 1024];   // [ diag(g_slots)Wqk | w_hh^T ]
__device__ float g_c1cat[1024];
__device__ float g_c2cat[1024];
__device__ float g_W1g[1024 * 256];    // W1 cols scaled by g_mlp
__device__ float g_c1m[1024];
__device__ float g_c2m[1024];
__device__ float g_Wvih[768 * 256];    // w_ih @ Wv

// ================= pipelined fp32 GEMM, 64x64x16 tiles, f32x2 FFMA =================
// C[M,N] = A[M,K] @ op(B).  bTrans=1: B[N,K]; bTrans=0: B[K,N].
// DO_LN: compute per-row LN stats of A in-GEMM; epilogue for n<lnCols applies
//   v = rstd*(v - mu*c1[n]);  then always v += c2[n] (c2 also carries plain bias).
//   Optional second output C2 for cols >= splitN (col index rebased).
// non-LN: optional rowden (v /= rowden[m]), bias at blockIdx.z==0, atomicOut.
template<int DO_LN>
__global__ void __launch_bounds__(256) gemm2_k(
    const float* __restrict__ A, const float* __restrict__ B,
    float* __restrict__ C, int ldc, float* __restrict__ C2, int ldc2, int splitN,
    int N, int K, int kLen, int bTrans,
    const float* __restrict__ c1, const float* __restrict__ c2, int lnCols,
    const float* __restrict__ rowden, const float* __restrict__ bias,
    int relu, int atomicOut)
{
    constexpr int TK = 16;
    __shared__ float As[2][TK][68];
    __shared__ float Bs[2][TK][68];
    __shared__ float smu[64], srs[64];
    int tid = threadIdx.x;
    int tx = tid & 15, ty = tid >> 4;
    int m0 = blockIdx.x * 64, n0 = blockIdx.y * 64;
    int kbeg = blockIdx.z * kLen;
    int nk = kLen / TK;
    int ra = tid >> 2, qa = tid & 3;
    int rb = tid >> 4, qb = tid & 15;

    const float* Aptr = A + (size_t)(m0 + ra) * K + kbeg + 4 * qa;
    const float* BptrT = B + (size_t)(n0 + ra) * K + kbeg + 4 * qa;
    const float* BptrN = B + (size_t)(kbeg + rb) * N + n0 + 4 * qb;

    float s1 = 0.f, s2 = 0.f;
    u64 acc[4][2];
#pragma unroll
    for (int i = 0; i < 4; i++) { acc[i][0] = 0ull; acc[i][1] = 0ull; }

    // prologue: tile 0
    float4 va = *(const float4*)Aptr;
    float4 vb = bTrans ? *(const float4*)BptrT : *(const float4*)BptrN;
    As[0][4 * qa + 0][ra] = va.x; As[0][4 * qa + 1][ra] = va.y;
    As[0][4 * qa + 2][ra] = va.z; As[0][4 * qa + 3][ra] = va.w;
    if (DO_LN) {
        s1 += va.x + va.y + va.z + va.w;
        s2 += va.x * va.x + va.y * va.y + va.z * va.z + va.w * va.w;
    }
    if (bTrans) {
        Bs[0][4 * qa + 0][ra] = vb.x; Bs[0][4 * qa + 1][ra] = vb.y;
        Bs[0][4 * qa + 2][ra] = vb.z; Bs[0][4 * qa + 3][ra] = vb.w;
    } else {
        *(float4*)&Bs[0][rb][4 * qb] = vb;
    }
    __syncthreads();

    for (int t = 0; t < nk; t++) {
        int cur = t & 1;
        bool has = (t + 1 < nk);
        if (has) {
            va = *(const float4*)(Aptr + (t + 1) * TK);
            vb = bTrans ? *(const float4*)(BptrT + (t + 1) * TK)
                        : *(const float4*)(BptrN + (size_t)(t + 1) * TK * N);
        }
#pragma unroll
        for (int kk = 0; kk < TK; kk++) {
            float4 a4 = *(const float4*)&As[cur][kk][ty * 4];
            float4 b4 = *(const float4*)&Bs[cur][kk][tx * 4];
            u64 b0 = pk2(b4.x, b4.y), b1p = pk2(b4.z, b4.w);
            float am[4] = {a4.x, a4.y, a4.z, a4.w};
#pragma unroll
            for (int i = 0; i < 4; i++) {
                u64 a2 = pk2(am[i], am[i]);
                acc[i][0] = fma2_(a2, b0, acc[i][0]);
                acc[i][1] = fma2_(a2, b1p, acc[i][1]);
            }
        }
        if (has) {
            int nb = cur ^ 1;
            As[nb][4 * qa + 0][ra] = va.x; As[nb][4 * qa + 1][ra] = va.y;
            As[nb][4 * qa + 2][ra] = va.z; As[nb][4 * qa + 3][ra] = va.w;
            if (DO_LN) {
                s1 += va.x + va.y + va.z + va.w;
                s2 += va.x * va.x + va.y * va.y + va.z * va.z + va.w * va.w;
            }
            if (bTrans) {
                Bs[nb][4 * qa + 0][ra] = vb.x; Bs[nb][4 * qa + 1][ra] = vb.y;
                Bs[nb][4 * qa + 2][ra] = vb.z; Bs[nb][4 * qa + 3][ra] = vb.w;
            } else {
                *(float4*)&Bs[nb][rb][4 * qb] = vb;
            }
            __syncthreads();
        }
    }

    if (DO_LN) {
        // quad holds full row ra: reduce over the 4 lanes
        s1 += __shfl_xor_sync(~0u, s1, 1); s2 += __shfl_xor_sync(~0u, s2, 1);
        s1 += __shfl_xor_sync(~0u, s1, 2); s2 += __shfl_xor_sync(~0u, s2, 2);
        if ((tid & 3) == 0) {
            float mu = s1 * (1.f / 256.f);
            float var = fmaf(-mu, mu, s2 * (1.f / 256.f));
            smu[ra] = mu;
            srs[ra] = rsqrtf(var + 1e-5f);
        }
        __syncthreads();
    }

#pragma unroll
    for (int i = 0; i < 4; i++) {
        int m = m0 + ty * 4 + i;
        float c[4];
        upk2(acc[i][0], c[0], c[1]);
        upk2(acc[i][1], c[2], c[3]);
        if (DO_LN) {
            float mu = smu[ty * 4 + i], rstd = srs[ty * 4 + i];
#pragma unroll
            for (int j = 0; j < 4; j++) {
                int n = n0 + tx * 4 + j;
                float v = c[j];
                if (n < lnCols) v = rstd * (v - mu * c1[n]);
                v += c2[n];
                if (relu) v = fmaxf(v, 0.f);
                if (C2 && n >= splitN) C2[(size_t)m * ldc2 + (n - splitN)] = v;
                else C[(size_t)m * ldc + n] = v;
            }
        } else {
            float rsf = rowden ? __fdividef(1.f, rowden[m]) : 1.f;
#pragma unroll
            for (int j = 0; j < 4; j++) {
                int n = n0 + tx * 4 + j;
                float v = c[j];
                if (rowden) v *= rsf;
                if (bias && blockIdx.z == 0) v += bias[n];
                if (relu) v = fmaxf(v, 0.f);
                if (atomicOut) atomicAdd(&C[(size_t)m * ldc + n], v);
                else C[(size_t)m * ldc + n] = v;
            }
        }
    }
}

// ---------------- C = A^T @ B  (A:[K,M], B:[K,N], both row-major) ----------------
__global__ void __launch_bounds__(256) gemm_tn_k(
    const float* __restrict__ A, const float* __restrict__ Bm, float* __restrict__ C,
    int M, int N, int K)
{
    constexpr int TM = 64, TN = 64, TK = 16;
    __shared__ __align__(16) float As[TK][TM + 8];
    __shared__ __align__(16) float Bs[TK][TN + 8];
    int tid = threadIdx.x;
    int tx = tid & 15, ty = tid >> 4;
    int m0 = blockIdx.x * TM, n0 = blockIdx.y * TN;

    u64 acc[4][2];
#pragma unroll
    for (int i = 0; i < 4; i++) { acc[i][0] = 0ull; acc[i][1] = 0ull; }

    for (int k0 = 0; k0 < K; k0 += TK) {
        int r = tid >> 4, q = tid & 15;
        *(float4*)&As[r][4 * q] = *(const float4*)(A + (size_t)(k0 + r) * M + m0 + 4 * q);
        *(float4*)&Bs[r][4 * q] = *(const float4*)(Bm + (size_t)(k0 + r) * N + n0 + 4 * q);
        __syncthreads();
#pragma unroll
        for (int kk = 0; kk < TK; kk++) {
            float4 bv = *(const float4*)&Bs[kk][tx * 4];
            u64 b0 = pk2(bv.x, bv.y), b1 = pk2(bv.z, bv.w);
#pragma unroll
            for (int i = 0; i < 4; i++) {
                float a = As[kk][ty * 4 + i];
                u64 a2 = pk2(a, a);
                acc[i][0] = fma2_(a2, b0, acc[i][0]);
                acc[i][1] = fma2_(a2, b1, acc[i][1]);
            }
        }
        __syncthreads();
    }
#pragma unroll
    for (int i = 0; i < 4; i++) {
        int m = m0 + ty * 4 + i;
        float c[4];
        upk2(acc[i][0], c[0], c[1]);
        upk2(acc[i][1], c[2], c[3]);
#pragma unroll
        for (int j = 0; j < 4; j++)
            C[(size_t)m * N + n0 + tx * 4 + j] = c[j];
    }
}

// ---------------- precompute builders ----------------
// Bcat[k][n] = g_slots[k]*Wqk[k][n] for n<256; c1cat[n]+=g*w; c2cat[n]+=b*w
__global__ void build_qk_k(const float* __restrict__ Wqk,
                           const float* __restrict__ g, const float* __restrict__ b,
                           float* __restrict__ Bcat,
                           float* __restrict__ c1, float* __restrict__ c2)
{
    int n = threadIdx.x;
    int k0 = blockIdx.x * 16;
    float lc1 = 0.f, lc2 = 0.f;
#pragma unroll
    for (int r = 0; r < 16; r++) {
        int k = k0 + r;
        float w = Wqk[(size_t)k * 256 + n];
        float gw = g[k] * w;
        Bcat[(size_t)k * 1024 + n] = gw;
        lc1 += gw;
        lc2 += b[k] * w;
    }
    atomicAdd(&c1[n], lc1);
    atomicAdd(&c2[n], lc2);
}

// transpose w_hh [768,256] into Bcat cols 256..1023: Bcat[k][256+n] = w_hh[n][k]
__global__ void build_hh_k(const float* __restrict__ whh, float* __restrict__ Bcat)
{
    __shared__ float tile[32][33];
    int n0 = blockIdx.x * 32, k0 = blockIdx.y * 32;
    int tx = threadIdx.x, ty = threadIdx.y;  // 32 x 8
#pragma unroll
    for (int i = 0; i < 4; i++)
        tile[ty + 8 * i][tx] = whh[(size_t)(n0 + ty + 8 * i) * 256 + k0 + tx];
    __syncthreads();
#pragma unroll
    for (int i = 0; i < 4; i++)
        Bcat[(size_t)(k0 + ty + 8 * i) * 1024 + 256 + n0 + tx] = tile[tx][ty + 8 * i];
}

__global__ void init_cat_k(const float* __restrict__ bhh, float* __restrict__ c2)
{
    int i = blockIdx.x * 256 + threadIdx.x;
    if (i < 768) c2[256 + i] = bhh[i];
}

// W1g[n][k] = W1[n][k]*g_mlp[k];  c1m[n]=sum_k g*W1; c2m[n]=sum_k b*W1 + b1[n]
__global__ void build_w1_k(const float* __restrict__ W1, const float* __restrict__ g,
                           const float* __restrict__ b, const float* __restrict__ b1,
                           float* __restrict__ W1g, float* __restrict__ c1,
                           float* __restrict__ c2)
{
    int w = threadIdx.x >> 5, lane = threadIdx.x & 31;
    int row = blockIdx.x * 8 + w;
    float lc1 = 0.f, lc2 = 0.f;
#pragma unroll
    for (int j = 0; j < 8; j++) {
        int col = lane + 32 * j;
        float v = W1[(size_t)row * 256 + col];
        float sc = g[col] * v;
        W1g[(size_t)row * 256 + col] = sc;
        lc1 += sc;
        lc2 += b[col] * v;
    }
#pragma unroll
    for (int o = 16; o; o >>= 1) {
        lc1 += __shfl_xor_sync(~0u, lc1, o);
        lc2 += __shfl_xor_sync(~0u, lc2, o);
    }
    if (lane == 0) { c1[row] = lc1; c2[row] = lc2 + b1[row]; }
}

// ---------------- fused attention pass (unchanged from round 6) ----------------
__global__ void __launch_bounds__(256, 2) attn_fused_k(
    const float* __restrict__ features, const float* __restrict__ qk,
    const float* __restrict__ gfeat, const float* __restrict__ bfeat,
    float* __restrict__ attn_out, float* __restrict__ U, float* __restrict__ rowsum)
{
    __shared__ float fs[32][257];
    __shared__ float ds[32][9];
    __shared__ float as_[8][33];
    int tid = threadIdx.x, lane = tid & 31, w = tid >> 5;
    int b = blockIdx.y;
    int n0 = blockIdx.x * 128;
    int sg = w & 1, rg = w >> 1;

    float gr[8], br[8];
#pragma unroll
    for (int j = 0; j < 8; j++) { gr[j] = gfeat[lane + 32 * j]; br[j] = bfeat[lane + 32 * j]; }

    u64 qkr2[4][4];
#pragma unroll
    for (int i = 0; i < 4; i++) {
        const float* qp = qk + ((size_t)(b * 8 + 4 * sg + i) << 8) + lane;
#pragma unroll
        for (int jj = 0; jj < 4; jj++)
            qkr2[i][jj] = pk2(qp[64 * jj], qp[64 * jj + 32]);
    }

    u64 u2[4][4];
#pragma unroll
    for (int i = 0; i < 4; i++)
#pragma unroll
        for (int jj = 0; jj < 4; jj++) u2[i][jj] = 0ull;
    float rs_acc[8];
#pragma unroll
    for (int i = 0; i < 8; i++) rs_acc[i] = 0.f;

    for (int t = 0; t < 4; t++) {
        const float* fp = features + ((size_t)b * kN + n0 + t * 32 + 4 * w) * 256 + lane;
#pragma unroll
        for (int rr = 0; rr < 4; rr++) {
            float x[8];
#pragma unroll
            for (int j = 0; j < 8; j++) x[j] = fp[(size_t)rr * 256 + 32 * j];
            float s1 = 0.f, s2 = 0.f;
#pragma unroll
            for (int j = 0; j < 8; j++) { s1 += x[j]; s2 = fmaf(x[j], x[j], s2); }
#pragma unroll
            for (int o = 16; o; o >>= 1) {
                s1 += __shfl_xor_sync(~0u, s1, o);
                s2 += __shfl_xor_sync(~0u, s2, o);
            }
            float mu = s1 * (1.f / 256.f);
            float var = fmaf(-mu, mu, s2 * (1.f / 256.f));
            float rstd = rsqrtf(var + 1e-5f);
#pragma unroll
            for (int j = 0; j < 8; j++)
                fs[4 * w + rr][lane + 32 * j] = fmaf((x[j] - mu) * rstd, gr[j], br[j]);
        }
        __syncthreads();
#pragma unroll
        for (int rr = 0; rr < 8; rr++) {
            int row = 8 * rg + rr;
            u64 f2[4];
#pragma unroll
            for (int jj = 0; jj < 4; jj++)
                f2[jj] = pk2(fs[row][lane + 64 * jj], fs[row][lane + 64 * jj + 32]);
#pragma unroll
            for (int i = 0; i < 4; i++) {
                u64 d2 = 0ull;
#pragma unroll
                for (int jj = 0; jj < 4; jj++) d2 = fma2_(qkr2[i][jj], f2[jj], d2);
                float lo, hi; upk2(d2, lo, hi);
                float d = lo + hi;
#pragma unroll
                for (int o = 16; o; o >>= 1) d += __shfl_xor_sync(~0u, d, o);
                if (lane == 0) ds[row][4 * sg + i] = d;
            }
        }
        __syncthreads();
        if (w == 0) {
            float dd[8];
#pragma unroll
            for (int i = 0; i < 8; i++) dd[i] = ds[lane][i];
            float mx = dd[0];
#pragma unroll
            for (int i = 1; i < 8; i++) mx = fmaxf(mx, dd[i]);
            float e[8], sum = 0.f;
#pragma unroll
            for (int i = 0; i < 8; i++) { e[i] = __expf(0.0625f * (dd[i] - mx)); sum += e[i]; }
            float inv = __fdividef(1.f, sum);
#pragma unroll
            for (int i = 0; i < 8; i++) {
                float a = fmaf(e[i], inv, 1e-8f);
                rs_acc[i] += a;
                as_[i][lane] = a;
                attn_out[(size_t)(b * 8 + i) * 4096 + n0 + t * 32 + lane] = a;
            }
        }
        __syncthreads();
#pragma unroll
        for (int rr = 0; rr < 8; rr++) {
            int row = 8 * rg + rr;
            u64 f2[4];
#pragma unroll
            for (int jj = 0; jj < 4; jj++)
                f2[jj] = pk2(fs[row][lane + 64 * jj], fs[row][lane + 64 * jj + 32]);
#pragma unroll
            for (int i = 0; i < 4; i++) {
                float a = as_[4 * sg + i][row];
                u64 a2 = pk2(a, a);
#pragma unroll
                for (int jj = 0; jj < 4; jj++) u2[i][jj] = fma2_(a2, f2[jj], u2[i][jj]);
            }
        }
        __syncthreads();
    }

    float* fsU = &fs[0][0];
#pragma unroll
    for (int i = 0; i < 8; i++) fsU[i * 257 + tid] = 0.f;
    __syncthreads();
#pragma unroll
    for (int i = 0; i < 4; i++)
#pragma unroll
        for (int jj = 0; jj < 4; jj++) {
            float lo, hi; upk2(u2[i][jj], lo, hi);
            atomicAdd(&fsU[(4 * sg + i) * 257 + lane + 64 * jj], lo);
            atomicAdd(&fsU[(4 * sg + i) * 257 + lane + 64 * jj + 32], hi);
        }
    __syncthreads();
#pragma unroll
    for (int i = 0; i < 8; i++)
        atomicAdd(&U[((size_t)(b * 8 + i) << 8) + tid], fsU[i * 257 + tid]);
    if (w == 0) {
#pragma unroll
        for (int i = 0; i < 8; i++) {
            float v = rs_acc[i];
#pragma unroll
            for (int o = 16; o; o >>= 1) v += __shfl_xor_sync(~0u, v, o);
            if (lane == 0) atomicAdd(&rowsum[b * 8 + i], v);
        }
    }
}

// ---------------- GRU cell elementwise (in-place on slots) ----------------
__global__ void gru_k(const float* __restrict__ gi, const float* __restrict__ gh,
                      float* __restrict__ slots)
{
    int row = blockIdx.x, c = threadIdx.x;
    size_t base = (size_t)row * 768 + c;
    float ir = gi[base], iz = gi[base + 256], in_ = gi[base + 512];
    float hr = gh[base], hz = gh[base + 256], hn = gh[base + 512];
    float r = 1.f / (1.f + __expf(-(ir + hr)));
    float z = 1.f / (1.f + __expf(-(iz + hz)));
    float nn = tanhf(fmaf(r, hn, in_));
    float h = slots[(size_t)row * 256 + c];
    slots[(size_t)row * 256 + c] = fmaf(z, h - nn, nn);
}

// ---------------- launcher ----------------
extern "C" void kernel_launch(void* const* d_in, const int* in_sizes, int n_in,
                              void* d_out, int out_size)
{
    const float* features   = (const float*)d_in[0];
    const float* slots_init = (const float*)d_in[1];
    const float* g_feat     = (const float*)d_in[2];
    const float* b_feat     = (const float*)d_in[3];
    const float* g_slots    = (const float*)d_in[4];
    const float* b_slots    = (const float*)d_in[5];
    const float* g_mlp      = (const float*)d_in[6];
    const float* b_mlp      = (const float*)d_in[7];
    const float* Wk         = (const float*)d_in[8];
    const float* Wv         = (const float*)d_in[9];
    const float* Wq         = (const float*)d_in[10];
    const float* w_ih       = (const float*)d_in[11];
    const float* w_hh       = (const float*)d_in[12];
    const float* b_ih       = (const float*)d_in[13];
    const float* b_hh       = (const float*)d_in[14];
    const float* W1         = (const float*)d_in[15];
    const float* b1         = (const float*)d_in[16];
    const float* W2         = (const float*)d_in[17];
    const float* b2         = (const float*)d_in[18];

    float* out       = (float*)d_out;
    float* out_slots = out;                         // [64,8,256]
    float* out_attn  = out + (size_t)64 * 8 * 256;  // [64,8,4096]

    float *slots, *qkbuf, *U, *rowsum, *gi, *gh, *hbuf;
    float *Wqk, *Bcat, *c1cat, *c2cat, *W1g, *c1m, *c2m, *Wvih;
    cudaGetSymbolAddress((void**)&slots, g_slots_buf);
    cudaGetSymbolAddress((void**)&qkbuf, g_qkbuf);
    cudaGetSymbolAddress((void**)&U, g_Ubuf);
    cudaGetSymbolAddress((void**)&rowsum, g_rowsum);
    cudaGetSymbolAddress((void**)&gi, g_gi);
    cudaGetSymbolAddress((void**)&gh, g_gh);
    cudaGetSymbolAddress((void**)&hbuf, g_hbuf);
    cudaGetSymbolAddress((void**)&Wqk, g_Wqk);
    cudaGetSymbolAddress((void**)&Bcat, g_Bcat);
    cudaGetSymbolAddress((void**)&c1cat, g_c1cat);
    cudaGetSymbolAddress((void**)&c2cat, g_c2cat);
    cudaGetSymbolAddress((void**)&W1g, g_W1g);
    cudaGetSymbolAddress((void**)&c1m, g_c1m);
    cudaGetSymbolAddress((void**)&c2m, g_c2m);
    cudaGetSymbolAddress((void**)&Wvih, g_Wvih);

    // ---- precompute folded weights ----
    cudaMemsetAsync(c1cat, 0, 1024 * 4, 0);
    cudaMemsetAsync(c2cat, 0, 1024 * 4, 0);
    gemm_tn_k<<<dim3(4, 4), 256>>>(Wq, Wk, Wqk, 256, 256, 256);
    build_qk_k<<<16, 256>>>(Wqk, g_slots, b_slots, Bcat, c1cat, c2cat);
    build_hh_k<<<dim3(24, 8), dim3(32, 8)>>>(w_hh, Bcat);
    init_cat_k<<<3, 256>>>(b_hh, c2cat);
    build_w1_k<<<128, 256>>>(W1, g_mlp, b_mlp, b1, W1g, c1m, c2m);
    gemm2_k<0><<<dim3(12, 4), 256>>>(w_ih, Wv, Wvih, 256, nullptr, 0, 1 << 30,
                                     256, 256, 256, 0,
                                     nullptr, nullptr, 0, nullptr, nullptr, 0, 0);

    cudaMemcpyAsync(slots, slots_init, (size_t)512 * 256 * 4,
                    cudaMemcpyDeviceToDevice, 0);

    for (int it = 0; it < kNITER; it++) {
        cudaMemsetAsync(U, 0, (size_t)512 * 256 * 4, 0);
        cudaMemsetAsync(rowsum, 0, (size_t)512 * 4, 0);
        // [qk | gh] = LN(slots)@Wqk  |  slots@w_hh^T + b_hh   (one GEMM, N=1024)
        gemm2_k<1><<<dim3(8, 16), 256>>>(slots, Bcat, qkbuf, 256, gh, 768, 256,
                                         1024, 256, 256, 0,
                                         c1cat, c2cat, 256, nullptr, nullptr, 0, 0);
        // fused big pass over features
        attn_fused_k<<<dim3(32, 64), 256>>>(features, qkbuf, g_feat, b_feat,
                                            out_attn, U, rowsum);
        // gi = (U @ Wvih^T)/rowsum + b_ih
        gemm2_k<0><<<dim3(8, 12), 256>>>(U, Wvih, gi, 768, nullptr, 0, 1 << 30,
                                         768, 256, 256, 1,
                                         nullptr, nullptr, 0, rowsum, b_ih, 0, 0);
        // GRU update (in place)
        gru_k<<<512, 256>>>(gi, gh, slots);
        // h = relu(LN(slots)@W1^T + b1)  via folded W1g/c1m/c2m
        gemm2_k<1><<<dim3(8, 16), 256>>>(slots, W1g, hbuf, 1024, nullptr, 0, 1 << 30,
                                         1024, 256, 256, 1,
                                         c1m, c2m, 1024, nullptr, nullptr, 1, 0);
        // slots += h @ W2^T + b2   (split-K=4, atomic accumulate)
        gemm2_k<0><<<dim3(8, 4, 4), 256>>>(hbuf, W2, slots, 256, nullptr, 0, 1 << 30,
                                           256, 1024, 256, 1,
                                           nullptr, nullptr, 0, nullptr, b2, 0, 1);
    }
    cudaMemcpyAsync(out_slots, slots, (size_t)512 * 256 * 4,
                    cudaMemcpyDeviceToDevice, 0);
}

// round 8
// speedup vs baseline: 1.7973x; 1.0072x over previous
#include <cuda_runtime.h>
#include <cstdint>
#include <cstddef>

#define kB 64
#define kN 4096
#define kS 8
#define kD 256
#define kM 1024
#define kNITER 3

typedef unsigned long long u64;

// ---------------- f32x2 packed math helpers ----------------
__device__ __forceinline__ u64 pk2(float lo, float hi) {
    u64 r;
    asm("mov.b64 %0, {%1,%2};" : "=l"(r)
        : "r"(__float_as_uint(lo)), "r"(__float_as_uint(hi)));
    return r;
}
__device__ __forceinline__ void upk2(u64 v, float& lo, float& hi) {
    unsigned a, b;
    asm("mov.b64 {%0,%1}, %2;" : "=r"(a), "=r"(b) : "l"(v));
    lo = __uint_as_float(a); hi = __uint_as_float(b);
}
__device__ __forceinline__ u64 fma2_(u64 a, u64 b, u64 c) {
    u64 d;
    asm("fma.rn.f32x2 %0, %1, %2, %3;" : "=l"(d) : "l"(a), "l"(b), "l"(c));
    return d;
}

// ---------------- scratch ----------------
__device__ float g_S0[512 * 256];          // post-GRU slots
__device__ float g_S1[512 * 256];          // final slots (post-MLP)
__device__ float g_qkbuf[512 * 256];
__device__ float g_Ubuf[512 * 256];
__device__ float g_rowsum[512];
__device__ float g_gh[512 * 768];
__device__ float g_Wqk[256 * 256];
__device__ float g_Bcat[256 * 1024];       // [ diag(g_slots)Wqk | w_hh^T ]
__device__ float g_c1cat[1024];
__device__ float g_c2cat[1024];
__device__ float g_W1g[1024 * 256];
__device__ float g_c1m[1024];
__device__ float g_c2m[1024];
__device__ float g_Wvih[768 * 256];        // w_ih @ Wv

// ================= pipelined fp32 GEMM, 64x64x16 tiles =================
// bTrans=1: C = A@B^T (B[N,K]); bTrans=0: C = A@B (B[K,N]).
// DO_LN: in-GEMM LN stats of A rows; epilogue v = rstd*(v-mu*c1[n]) for n<lnCols,
// then v += c2[n]; optional second output C2 for n>=splitN.
// Side job: zeroU/zeroRS zeroed by y==0 blocks.
template<int DO_LN>
__global__ void __launch_bounds__(256) gemm2_k(
    const float* __restrict__ A, const float* __restrict__ B,
    float* __restrict__ C, int ldc, float* __restrict__ C2, int ldc2, int splitN,
    int N, int K, int kLen, int bTrans,
    const float* __restrict__ c1, const float* __restrict__ c2, int lnCols,
    const float* __restrict__ rowden, const float* __restrict__ bias,
    int relu, int atomicOut, float* __restrict__ zeroU, float* __restrict__ zeroRS)
{
    constexpr int TK = 16;
    __shared__ float As[2][TK][68];
    __shared__ float Bs[2][TK][68];
    __shared__ float smu[64], srs[64];
    int tid = threadIdx.x;
    int tx = tid & 15, ty = tid >> 4;
    int m0 = blockIdx.x * 64, n0 = blockIdx.y * 64;
    int kbeg = blockIdx.z * kLen;
    int nk = kLen / TK;
    int ra = tid >> 2, qa = tid & 3;
    int rb = tid >> 4, qb = tid & 15;

    if (zeroU && blockIdx.y == 0 && blockIdx.z == 0) {
        float4 z4 = make_float4(0.f, 0.f, 0.f, 0.f);
#pragma unroll
        for (int s = 0; s < 16; s++)
            *(float4*)(zeroU + (size_t)m0 * 256 + s * 1024 + tid * 4) = z4;
        if (blockIdx.x == 0 && tid < 128)
            *(float4*)(zeroRS + tid * 4) = z4;
    }

    const float* Aptr = A + (size_t)(m0 + ra) * K + kbeg + 4 * qa;
    const float* BptrT = B + (size_t)(n0 + ra) * K + kbeg + 4 * qa;
    const float* BptrN = B + (size_t)(kbeg + rb) * N + n0 + 4 * qb;

    float s1 = 0.f, s2 = 0.f;
    u64 acc[4][2];
#pragma unroll
    for (int i = 0; i < 4; i++) { acc[i][0] = 0ull; acc[i][1] = 0ull; }

    float4 va = *(const float4*)Aptr;
    float4 vb = bTrans ? *(const float4*)BptrT : *(const float4*)BptrN;
    As[0][4 * qa + 0][ra] = va.x; As[0][4 * qa + 1][ra] = va.y;
    As[0][4 * qa + 2][ra] = va.z; As[0][4 * qa + 3][ra] = va.w;
    if (DO_LN) {
        s1 += va.x + va.y + va.z + va.w;
        s2 += va.x * va.x + va.y * va.y + va.z * va.z + va.w * va.w;
    }
    if (bTrans) {
        Bs[0][4 * qa + 0][ra] = vb.x; Bs[0][4 * qa + 1][ra] = vb.y;
        Bs[0][4 * qa + 2][ra] = vb.z; Bs[0][4 * qa + 3][ra] = vb.w;
    } else {
        *(float4*)&Bs[0][rb][4 * qb] = vb;
    }
    __syncthreads();

    for (int t = 0; t < nk; t++) {
        int cur = t & 1;
        bool has = (t + 1 < nk);
        if (has) {
            va = *(const float4*)(Aptr + (t + 1) * TK);
            vb = bTrans ? *(const float4*)(BptrT + (t + 1) * TK)
                        : *(const float4*)(BptrN + (size_t)(t + 1) * TK * N);
        }
#pragma unroll
        for (int kk = 0; kk < TK; kk++) {
            float4 a4 = *(const float4*)&As[cur][kk][ty * 4];
            float4 b4 = *(const float4*)&Bs[cur][kk][tx * 4];
            u64 b0 = pk2(b4.x, b4.y), b1p = pk2(b4.z, b4.w);
            float am[4] = {a4.x, a4.y, a4.z, a4.w};
#pragma unroll
            for (int i = 0; i < 4; i++) {
                u64 a2 = pk2(am[i], am[i]);
                acc[i][0] = fma2_(a2, b0, acc[i][0]);
                acc[i][1] = fma2_(a2, b1p, acc[i][1]);
            }
        }
        if (has) {
            int nb = cur ^ 1;
            As[nb][4 * qa + 0][ra] = va.x; As[nb][4 * qa + 1][ra] = va.y;
            As[nb][4 * qa + 2][ra] = va.z; As[nb][4 * qa + 3][ra] = va.w;
            if (DO_LN) {
                s1 += va.x + va.y + va.z + va.w;
                s2 += va.x * va.x + va.y * va.y + va.z * va.z + va.w * va.w;
            }
            if (bTrans) {
                Bs[nb][4 * qa + 0][ra] = vb.x; Bs[nb][4 * qa + 1][ra] = vb.y;
                Bs[nb][4 * qa + 2][ra] = vb.z; Bs[nb][4 * qa + 3][ra] = vb.w;
            } else {
                *(float4*)&Bs[nb][rb][4 * qb] = vb;
            }
            __syncthreads();
        }
    }

    if (DO_LN) {
        s1 += __shfl_xor_sync(~0u, s1, 1); s2 += __shfl_xor_sync(~0u, s2, 1);
        s1 += __shfl_xor_sync(~0u, s1, 2); s2 += __shfl_xor_sync(~0u, s2, 2);
        if ((tid & 3) == 0) {
            float mu = s1 * (1.f / 256.f);
            float var = fmaf(-mu, mu, s2 * (1.f / 256.f));
            smu[ra] = mu;
            srs[ra] = rsqrtf(var + 1e-5f);
        }
        __syncthreads();
    }

#pragma unroll
    for (int i = 0; i < 4; i++) {
        int m = m0 + ty * 4 + i;
        float c[4];
        upk2(acc[i][0], c[0], c[1]);
        upk2(acc[i][1], c[2], c[3]);
        if (DO_LN) {
            float mu = smu[ty * 4 + i], rstd = srs[ty * 4 + i];
#pragma unroll
            for (int j = 0; j < 4; j++) {
                int n = n0 + tx * 4 + j;
                float v = c[j];
                if (n < lnCols) v = rstd * (v - mu * c1[n]);
                v += c2[n];
                if (relu) v = fmaxf(v, 0.f);
                if (C2 && n >= splitN) C2[(size_t)m * ldc2 + (n - splitN)] = v;
                else C[(size_t)m * ldc + n] = v;
            }
        } else {
            float rsf = rowden ? __fdividef(1.f, rowden[m]) : 1.f;
#pragma unroll
            for (int j = 0; j < 4; j++) {
                int n = n0 + tx * 4 + j;
                float v = c[j];
                if (rowden) v *= rsf;
                if (bias && blockIdx.z == 0) v += bias[n];
                if (relu) v = fmaxf(v, 0.f);
                if (atomicOut) atomicAdd(&C[(size_t)m * ldc + n], v);
                else C[(size_t)m * ldc + n] = v;
            }
        }
    }
}

// ---------------- C = A^T @ B  (A:[K,M], B:[K,N]) ----------------
__global__ void __launch_bounds__(256) gemm_tn_k(
    const float* __restrict__ A, const float* __restrict__ Bm, float* __restrict__ C,
    int M, int N, int K)
{
    constexpr int TK = 16;
    __shared__ __align__(16) float As[TK][72];
    __shared__ __align__(16) float Bs[TK][72];
    int tid = threadIdx.x;
    int tx = tid & 15, ty = tid >> 4;
    int m0 = blockIdx.x * 64, n0 = blockIdx.y * 64;

    u64 acc[4][2];
#pragma unroll
    for (int i = 0; i < 4; i++) { acc[i][0] = 0ull; acc[i][1] = 0ull; }

    for (int k0 = 0; k0 < K; k0 += TK) {
        int r = tid >> 4, q = tid & 15;
        *(float4*)&As[r][4 * q] = *(const float4*)(A + (size_t)(k0 + r) * M + m0 + 4 * q);
        *(float4*)&Bs[r][4 * q] = *(const float4*)(Bm + (size_t)(k0 + r) * N + n0 + 4 * q);
        __syncthreads();
#pragma unroll
        for (int kk = 0; kk < TK; kk++) {
            float4 bv = *(const float4*)&Bs[kk][tx * 4];
            u64 b0 = pk2(bv.x, bv.y), b1 = pk2(bv.z, bv.w);
#pragma unroll
            for (int i = 0; i < 4; i++) {
                float a = As[kk][ty * 4 + i];
                u64 a2 = pk2(a, a);
                acc[i][0] = fma2_(a2, b0, acc[i][0]);
                acc[i][1] = fma2_(a2, b1, acc[i][1]);
            }
        }
        __syncthreads();
    }
#pragma unroll
    for (int i = 0; i < 4; i++) {
        int m = m0 + ty * 4 + i;
        float c[4];
        upk2(acc[i][0], c[0], c[1]);
        upk2(acc[i][1], c[2], c[3]);
#pragma unroll
        for (int j = 0; j < 4; j++)
            C[(size_t)m * N + n0 + tx * 4 + j] = c[j];
    }
}

// ---------------- merged precompute builder ----------------
// x in [0,16): qk fold (Bcat cols 0..255, c1cat/c2cat 0..255), no atomics
// x in [16,208): w_hh transpose into Bcat cols 256..1023
// x in [208,211): c2cat[256..1023] = b_hh
// x in [211,339): W1 fold
__global__ void __launch_bounds__(256) build_misc_k(
    const float* __restrict__ Wqk, const float* __restrict__ gs,
    const float* __restrict__ bs, const float* __restrict__ whh,
    const float* __restrict__ bhh,
    const float* __restrict__ W1, const float* __restrict__ gm,
    const float* __restrict__ bm, const float* __restrict__ b1,
    float* __restrict__ Bcat, float* __restrict__ c1cat, float* __restrict__ c2cat,
    float* __restrict__ W1g, float* __restrict__ c1m, float* __restrict__ c2m)
{
    int x = blockIdx.x;
    int tid = threadIdx.x;
    if (x < 16) {
        __shared__ float r1[16][17], r2[16][17];
        int nn = tid & 15, kg = tid >> 4;
        int n = 16 * x + nn;
        float lc1 = 0.f, lc2 = 0.f;
#pragma unroll
        for (int r = 0; r < 16; r++) {
            int k = kg * 16 + r;
            float w = Wqk[(size_t)k * 256 + n];
            float gw = gs[k] * w;
            Bcat[(size_t)k * 1024 + n] = gw;
            lc1 += gw;
            lc2 += bs[k] * w;
        }
        r1[kg][nn] = lc1; r2[kg][nn] = lc2;
        __syncthreads();
        if (kg == 0) {
            float a = 0.f, b = 0.f;
#pragma unroll
            for (int i = 0; i < 16; i++) { a += r1[i][nn]; b += r2[i][nn]; }
            c1cat[n] = a; c2cat[n] = b;
        }
    } else if (x < 208) {
        __shared__ float tile[32][33];
        int t = x - 16;
        int n0 = (t % 24) * 32, k0 = (t / 24) * 32;
        int tx = tid & 31, ty = tid >> 5;
#pragma unroll
        for (int i = 0; i < 4; i++)
            tile[ty + 8 * i][tx] = whh[(size_t)(n0 + ty + 8 * i) * 256 + k0 + tx];
        __syncthreads();
#pragma unroll
        for (int i = 0; i < 4; i++)
            Bcat[(size_t)(k0 + ty + 8 * i) * 1024 + 256 + n0 + tx] = tile[tx][ty + 8 * i];
    } else if (x < 211) {
        int i = (x - 208) * 256 + tid;
        if (i < 768) c2cat[256 + i] = bhh[i];
    } else {
        int w = tid >> 5, lane = tid & 31;
        int row = (x - 211) * 8 + w;
        float lc1 = 0.f, lc2 = 0.f;
#pragma unroll
        for (int j = 0; j < 8; j++) {
            int col = lane + 32 * j;
            float v = W1[(size_t)row * 256 + col];
            float sc = gm[col] * v;
            W1g[(size_t)row * 256 + col] = sc;
            lc1 += sc;
            lc2 += bm[col] * v;
        }
#pragma unroll
        for (int o = 16; o; o >>= 1) {
            lc1 += __shfl_xor_sync(~0u, lc1, o);
            lc2 += __shfl_xor_sync(~0u, lc2, o);
        }
        if (lane == 0) { c1m[row] = lc1; c2m[row] = lc2 + b1[row]; }
    }
}

// ---------------- fused attention pass ----------------
__global__ void __launch_bounds__(256, 2) attn_fused_k(
    const float* __restrict__ features, const float* __restrict__ qk,
    const float* __restrict__ gfeat, const float* __restrict__ bfeat,
    float* __restrict__ attn_out, float* __restrict__ U, float* __restrict__ rowsum)
{
    __shared__ float fs[32][257];
    __shared__ float ds[32][9];
    __shared__ float as_[8][33];
    int tid = threadIdx.x, lane = tid & 31, w = tid >> 5;
    int b = blockIdx.y;
    int n0 = blockIdx.x * 128;
    int sg = w & 1, rg = w >> 1;

    float gr[8], br[8];
#pragma unroll
    for (int j = 0; j < 8; j++) { gr[j] = gfeat[lane + 32 * j]; br[j] = bfeat[lane + 32 * j]; }

    u64 qkr2[4][4];
#pragma unroll
    for (int i = 0; i < 4; i++) {
        const float* qp = qk + ((size_t)(b * 8 + 4 * sg + i) << 8) + lane;
#pragma unroll
        for (int jj = 0; jj < 4; jj++)
            qkr2[i][jj] = pk2(qp[64 * jj], qp[64 * jj + 32]);
    }

    u64 u2[4][4];
#pragma unroll
    for (int i = 0; i < 4; i++)
#pragma unroll
        for (int jj = 0; jj < 4; jj++) u2[i][jj] = 0ull;
    float rs_acc[8];
#pragma unroll
    for (int i = 0; i < 8; i++) rs_acc[i] = 0.f;

    for (int t = 0; t < 4; t++) {
        const float* fp = features + ((size_t)b * kN + n0 + t * 32 + 4 * w) * 256 + lane;
#pragma unroll
        for (int rr = 0; rr < 4; rr++) {
            float x[8];
#pragma unroll
            for (int j = 0; j < 8; j++) x[j] = fp[(size_t)rr * 256 + 32 * j];
            float s1 = 0.f, s2 = 0.f;
#pragma unroll
            for (int j = 0; j < 8; j++) { s1 += x[j]; s2 = fmaf(x[j], x[j], s2); }
#pragma unroll
            for (int o = 16; o; o >>= 1) {
                s1 += __shfl_xor_sync(~0u, s1, o);
                s2 += __shfl_xor_sync(~0u, s2, o);
            }
            float mu = s1 * (1.f / 256.f);
            float var = fmaf(-mu, mu, s2 * (1.f / 256.f));
            float rstd = rsqrtf(var + 1e-5f);
#pragma unroll
            for (int j = 0; j < 8; j++)
                fs[4 * w + rr][lane + 32 * j] = fmaf((x[j] - mu) * rstd, gr[j], br[j]);
        }
        __syncthreads();
        // logits: merged shuffle-tree (9 shfl for 4 slots)
#pragma unroll
        for (int rr = 0; rr < 8; rr++) {
            int row = 8 * rg + rr;
            u64 f2[4];
#pragma unroll
            for (int jj = 0; jj < 4; jj++)
                f2[jj] = pk2(fs[row][lane + 64 * jj], fs[row][lane + 64 * jj + 32]);
            float d[4];
#pragma unroll
            for (int i = 0; i < 4; i++) {
                u64 d2 = 0ull;
#pragma unroll
                for (int jj = 0; jj < 4; jj++) d2 = fma2_(qkr2[i][jj], f2[jj], d2);
                float lo, hi; upk2(d2, lo, hi);
                d[i] = lo + hi;
            }
            d[0] += __shfl_xor_sync(~0u, d[0], 1);
            d[1] += __shfl_xor_sync(~0u, d[1], 1);
            float m01 = (lane & 1) ? d[1] : d[0];
            d[2] += __shfl_xor_sync(~0u, d[2], 1);
            d[3] += __shfl_xor_sync(~0u, d[3], 1);
            float m23 = (lane & 1) ? d[3] : d[2];
            m01 += __shfl_xor_sync(~0u, m01, 2);
            m23 += __shfl_xor_sync(~0u, m23, 2);
            float mm = (lane & 2) ? m23 : m01;
            mm += __shfl_xor_sync(~0u, mm, 4);
            mm += __shfl_xor_sync(~0u, mm, 8);
            mm += __shfl_xor_sync(~0u, mm, 16);
            if (lane < 4) ds[row][4 * sg + lane] = mm;
        }
        __syncthreads();
        if (w == 0) {
            float dd[8];
#pragma unroll
            for (int i = 0; i < 8; i++) dd[i] = ds[lane][i];
            float mx = dd[0];
#pragma unroll
            for (int i = 1; i < 8; i++) mx = fmaxf(mx, dd[i]);
            float e[8], sum = 0.f;
#pragma unroll
            for (int i = 0; i < 8; i++) { e[i] = __expf(0.0625f * (dd[i] - mx)); sum += e[i]; }
            float inv = __fdividef(1.f, sum);
#pragma unroll
            for (int i = 0; i < 8; i++) {
                float a = fmaf(e[i], inv, 1e-8f);
                rs_acc[i] += a;
                as_[i][lane] = a;
                attn_out[(size_t)(b * 8 + i) * 4096 + n0 + t * 32 + lane] = a;
            }
        }
        __syncthreads();
#pragma unroll
        for (int rr = 0; rr < 8; rr++) {
            int row = 8 * rg + rr;
            u64 f2[4];
#pragma unroll
            for (int jj = 0; jj < 4; jj++)
                f2[jj] = pk2(fs[row][lane + 64 * jj], fs[row][lane + 64 * jj + 32]);
#pragma unroll
            for (int i = 0; i < 4; i++) {
                float a = as_[4 * sg + i][row];
                u64 a2 = pk2(a, a);
#pragma unroll
                for (int jj = 0; jj < 4; jj++) u2[i][jj] = fma2_(a2, f2[jj], u2[i][jj]);
            }
        }
        __syncthreads();
    }

    float* fsU = &fs[0][0];
#pragma unroll
    for (int i = 0; i < 8; i++) fsU[i * 257 + tid] = 0.f;
    __syncthreads();
#pragma unroll
    for (int i = 0; i < 4; i++)
#pragma unroll
        for (int jj = 0; jj < 4; jj++) {
            float lo, hi; upk2(u2[i][jj], lo, hi);
            atomicAdd(&fsU[(4 * sg + i) * 257 + lane + 64 * jj], lo);
            atomicAdd(&fsU[(4 * sg + i) * 257 + lane + 64 * jj + 32], hi);
        }
    __syncthreads();
#pragma unroll
    for (int i = 0; i < 8; i++)
        atomicAdd(&U[((size_t)(b * 8 + i) << 8) + tid], fsU[i * 257 + tid]);
    if (w == 0) {
#pragma unroll
        for (int i = 0; i < 8; i++) {
            float v = rs_acc[i];
#pragma unroll
            for (int o = 16; o; o >>= 1) v += __shfl_xor_sync(~0u, v, o);
            if (lane == 0) atomicAdd(&rowsum[b * 8 + i], v);
        }
    }
}

// ---------------- fused gi-GEMM (3 gates) + GRU ----------------
// grid (8,4): block = rows m0..+63, cols c0..+63 of D.
// acc gates r,z,n: (U @ Wvih^T)[m][g*256+c]. Epilogue: GRU, write S0 & S1.
__global__ void __launch_bounds__(256) gru_gemm_k(
    const float* __restrict__ U, const float* __restrict__ Wvih,
    const float* __restrict__ rowsum, const float* __restrict__ b_ih,
    const float* __restrict__ gh, float* __restrict__ S0, float* __restrict__ S1)
{
    constexpr int TK = 16;
    __shared__ float As[2][TK][68];
    __shared__ float Bs[2][TK][208];
    int tid = threadIdx.x;
    int tx = tid & 15, ty = tid >> 4;
    int m0 = blockIdx.x * 64, c0 = blockIdx.y * 64;
    int ra = tid >> 2, qa = tid & 3;

    const float* Aptr = U + (size_t)(m0 + ra) * 256 + 4 * qa;

    u64 acc[3][4][2];
#pragma unroll
    for (int g = 0; g < 3; g++)
#pragma unroll
        for (int i = 0; i < 4; i++) { acc[g][i][0] = 0ull; acc[g][i][1] = 0ull; }

    float4 va = *(const float4*)Aptr;
    float4 vb[3];
#pragma unroll
    for (int g = 0; g < 3; g++)
        vb[g] = *(const float4*)(Wvih + (size_t)(g * 256 + c0 + ra) * 256 + 4 * qa);
    As[0][4 * qa + 0][ra] = va.x; As[0][4 * qa + 1][ra] = va.y;
    As[0][4 * qa + 2][ra] = va.z; As[0][4 * qa + 3][ra] = va.w;
#pragma unroll
    for (int g = 0; g < 3; g++) {
        Bs[0][4 * qa + 0][g * 64 + ra] = vb[g].x;
        Bs[0][4 * qa + 1][g * 64 + ra] = vb[g].y;
        Bs[0][4 * qa + 2][g * 64 + ra] = vb[g].z;
        Bs[0][4 * qa + 3][g * 64 + ra] = vb[g].w;
    }
    __syncthreads();

    for (int t = 0; t < 16; t++) {
        int cur = t & 1;
        bool has = (t + 1 < 16);
        if (has) {
            va = *(const float4*)(Aptr + (t + 1) * TK);
#pragma unroll
            for (int g = 0; g < 3; g++)
                vb[g] = *(const float4*)(Wvih + (size_t)(g * 256 + c0 + ra) * 256
                                         + (t + 1) * TK + 4 * qa);
        }
#pragma unroll
        for (int kk = 0; kk < TK; kk++) {
            float4 a4 = *(const float4*)&As[cur][kk][ty * 4];
            float am[4] = {a4.x, a4.y, a4.z, a4.w};
#pragma unroll
            for (int g = 0; g < 3; g++) {
                float4 b4 = *(const float4*)&Bs[cur][kk][g * 64 + tx * 4];
                u64 b0 = pk2(b4.x, b4.y), b1p = pk2(b4.z, b4.w);
#pragma unroll
                for (int i = 0; i < 4; i++) {
                    u64 a2 = pk2(am[i], am[i]);
                    acc[g][i][0] = fma2_(a2, b0, acc[g][i][0]);
                    acc[g][i][1] = fma2_(a2, b1p, acc[g][i][1]);
                }
            }
        }
        if (has) {
            int nb = cur ^ 1;
            As[nb][4 * qa + 0][ra] = va.x; As[nb][4 * qa + 1][ra] = va.y;
            As[nb][4 * qa + 2][ra] = va.z; As[nb][4 * qa + 3][ra] = va.w;
#pragma unroll
            for (int g = 0; g < 3; g++) {
                Bs[nb][4 * qa + 0][g * 64 + ra] = vb[g].x;
                Bs[nb][4 * qa + 1][g * 64 + ra] = vb[g].y;
                Bs[nb][4 * qa + 2][g * 64 + ra] = vb[g].z;
                Bs[nb][4 * qa + 3][g * 64 + ra] = vb[g].w;
            }
            __syncthreads();
        }
    }

#pragma unroll
    for (int i = 0; i < 4; i++) {
        int m = m0 + ty * 4 + i;
        float inv = __fdividef(1.f, rowsum[m]);
        float rg_[4], zg[4], ng[4];
        upk2(acc[0][i][0], rg_[0], rg_[1]); upk2(acc[0][i][1], rg_[2], rg_[3]);
        upk2(acc[1][i][0], zg[0], zg[1]);   upk2(acc[1][i][1], zg[2], zg[3]);
        upk2(acc[2][i][0], ng[0], ng[1]);   upk2(acc[2][i][1], ng[2], ng[3]);
#pragma unroll
        for (int j = 0; j < 4; j++) {
            int c = c0 + tx * 4 + j;
            float ir = fmaf(rg_[j], inv, b_ih[c]);
            float iz = fmaf(zg[j], inv, b_ih[256 + c]);
            float in_ = fmaf(ng[j], inv, b_ih[512 + c]);
            size_t gb = (size_t)m * 768 + c;
            float hr = gh[gb], hz = gh[gb + 256], hn = gh[gb + 512];
            float r = 1.f / (1.f + __expf(-(ir + hr)));
            float z = 1.f / (1.f + __expf(-(iz + hz)));
            float nv = tanhf(fmaf(r, hn, in_));
            float h = S1[(size_t)m * 256 + c];
            float v = fmaf(z, h - nv, nv);
            S0[(size_t)m * 256 + c] = v;
            S1[(size_t)m * 256 + c] = v;
        }
    }
}

// ---------------- fused MLP: h = relu(LN(S0)@W1g^T + ...), S1 += h@W2^T + b2 ----------------
// grid (8,16): block = rows m0..+63, h-cols h0..+63. Stage2 atomics into S1.
__global__ void __launch_bounds__(256) mlp_k(
    const float* __restrict__ S0, const float* __restrict__ W1g,
    const float* __restrict__ c1, const float* __restrict__ c2,
    const float* __restrict__ W2, const float* __restrict__ b2,
    float* __restrict__ S1)
{
    constexpr int TK = 16;
    __shared__ __align__(16) float sbuf[4352];  // stage1: As/Bs double-buffered; stage2: W2s[64][68]
    __shared__ float hs[64][68];
    __shared__ float smu[64], srs[64];
#define AS_(b,k,i) sbuf[(b) * 1088 + (k) * 68 + (i)]
#define BS_(b,k,i) sbuf[2176 + (b) * 1088 + (k) * 68 + (i)]
#define W2S_(k,o)  sbuf[(k) * 68 + (o)]
    int tid = threadIdx.x;
    int tx = tid & 15, ty = tid >> 4;
    int m0 = blockIdx.x * 64, h0 = blockIdx.y * 64;
    int ra = tid >> 2, qa = tid & 3;

    const float* Aptr = S0 + (size_t)(m0 + ra) * 256 + 4 * qa;
    const float* Bptr = W1g + (size_t)(h0 + ra) * 256 + 4 * qa;

    float s1 = 0.f, s2 = 0.f;
    u64 acc[4][2];
#pragma unroll
    for (int i = 0; i < 4; i++) { acc[i][0] = 0ull; acc[i][1] = 0ull; }

    float4 va = *(const float4*)Aptr;
    float4 vb = *(const float4*)Bptr;
    AS_(0, 4 * qa + 0, ra) = va.x; AS_(0, 4 * qa + 1, ra) = va.y;
    AS_(0, 4 * qa + 2, ra) = va.z; AS_(0, 4 * qa + 3, ra) = va.w;
    s1 += va.x + va.y + va.z + va.w;
    s2 += va.x * va.x + va.y * va.y + va.z * va.z + va.w * va.w;
    BS_(0, 4 * qa + 0, ra) = vb.x; BS_(0, 4 * qa + 1, ra) = vb.y;
    BS_(0, 4 * qa + 2, ra) = vb.z; BS_(0, 4 * qa + 3, ra) = vb.w;
    __syncthreads();

    for (int t = 0; t < 16; t++) {
        int cur = t & 1;
        bool has = (t + 1 < 16);
        if (has) {
            va = *(const float4*)(Aptr + (t + 1) * TK);
            vb = *(const float4*)(Bptr + (t + 1) * TK);
        }
#pragma unroll
        for (int kk = 0; kk < TK; kk++) {
            float4 a4 = *(const float4*)&AS_(cur, kk, ty * 4);
            float4 b4 = *(const float4*)&BS_(cur, kk, tx * 4);
            u64 b0 = pk2(b4.x, b4.y), b1p = pk2(b4.z, b4.w);
            float am[4] = {a4.x, a4.y, a4.z, a4.w};
#pragma unroll
            for (int i = 0; i < 4; i++) {
                u64 a2 = pk2(am[i], am[i]);
                acc[i][0] = fma2_(a2, b0, acc[i][0]);
                acc[i][1] = fma2_(a2, b1p, acc[i][1]);
            }
        }
        if (has) {
            int nb = cur ^ 1;
            AS_(nb, 4 * qa + 0, ra) = va.x; AS_(nb, 4 * qa + 1, ra) = va.y;
            AS_(nb, 4 * qa + 2, ra) = va.z; AS_(nb, 4 * qa + 3, ra) = va.w;
            s1 += va.x + va.y + va.z + va.w;
            s2 += va.x * va.x + va.y * va.y + va.z * va.z + va.w * va.w;
            BS_(nb, 4 * qa + 0, ra) = vb.x; BS_(nb, 4 * qa + 1, ra) = vb.y;
            BS_(nb, 4 * qa + 2, ra) = vb.z; BS_(nb, 4 * qa + 3, ra) = vb.w;
            __syncthreads();
        }
    }

    s1 += __shfl_xor_sync(~0u, s1, 1); s2 += __shfl_xor_sync(~0u, s2, 1);
    s1 += __shfl_xor_sync(~0u, s1, 2); s2 += __shfl_xor_sync(~0u, s2, 2);
    if ((tid & 3) == 0) {
        float mu = s1 * (1.f / 256.f);
        float var = fmaf(-mu, mu, s2 * (1.f / 256.f));
        smu[ra] = mu;
        srs[ra] = rsqrtf(var + 1e-5f);
    }
    __syncthreads();

    // h tile -> smem (relu)
#pragma unroll
    for (int i = 0; i < 4; i++) {
        float mu = smu[ty * 4 + i], rstd = srs[ty * 4 + i];
        float c[4];
        upk2(acc[i][0], c[0], c[1]);
        upk2(acc[i][1], c[2], c[3]);
#pragma unroll
        for (int j = 0; j < 4; j++) {
            int n = h0 + tx * 4 + j;
            float v = rstd * (c[j] - mu * c1[n]) + c2[n];
            hs[ty * 4 + i][tx * 4 + j] = fmaxf(v, 0.f);
        }
    }
    __syncthreads();

    // stage 2: out tiles of 64, W2 slice [64 out][64 k] in sbuf
    for (int ot = 0; ot < 4; ot++) {
        // load W2s[k][o]: thread -> o=ra, k chunk 16*qa..+15
#pragma unroll
        for (int tq = 0; tq < 4; tq++) {
            float4 w4 = *(const float4*)(W2 + (size_t)(ot * 64 + ra) * 1024 + h0
                                         + 16 * qa + 4 * tq);
            W2S_(16 * qa + 4 * tq + 0, ra) = w4.x;
            W2S_(16 * qa + 4 * tq + 1, ra) = w4.y;
            W2S_(16 * qa + 4 * tq + 2, ra) = w4.z;
            W2S_(16 * qa + 4 * tq + 3, ra) = w4.w;
        }
        __syncthreads();

        u64 acc2[4][2];
#pragma unroll
        for (int i = 0; i < 4; i++) { acc2[i][0] = 0ull; acc2[i][1] = 0ull; }
#pragma unroll
        for (int k4 = 0; k4 < 64; k4 += 4) {
            float4 h4[4];
#pragma unroll
            for (int i = 0; i < 4; i++)
                h4[i] = *(const float4*)&hs[ty * 4 + i][k4];
#pragma unroll
            for (int u = 0; u < 4; u++) {
                float4 b4 = *(const float4*)&W2S_(k4 + u, tx * 4);
                u64 b0 = pk2(b4.x, b4.y), b1p = pk2(b4.z, b4.w);
                float hm[4] = {
                    u == 0 ? h4[0].x : u == 1 ? h4[0].y : u == 2 ? h4[0].z : h4[0].w,
                    u == 0 ? h4[1].x : u == 1 ? h4[1].y : u == 2 ? h4[1].z : h4[1].w,
                    u == 0 ? h4[2].x : u == 1 ? h4[2].y : u == 2 ? h4[2].z : h4[2].w,
                    u == 0 ? h4[3].x : u == 1 ? h4[3].y : u == 2 ? h4[3].z : h4[3].w};
#pragma unroll
                for (int i = 0; i < 4; i++) {
                    u64 a2 = pk2(hm[i], hm[i]);
                    acc2[i][0] = fma2_(a2, b0, acc2[i][0]);
                    acc2[i][1] = fma2_(a2, b1p, acc2[i][1]);
                }
            }
        }
#pragma unroll
        for (int i = 0; i < 4; i++) {
            int m = m0 + ty * 4 + i;
            float c[4];
            upk2(acc2[i][0], c[0], c[1]);
            upk2(acc2[i][1], c[2], c[3]);
#pragma unroll
            for (int j = 0; j < 4; j++) {
                int n = ot * 64 + tx * 4 + j;
                float v = c[j];
                if (blockIdx.y == 0) v += b2[n];
                atomicAdd(&S1[(size_t)m * 256 + n], v);
            }
        }
        __syncthreads();
    }
#undef AS_
#undef BS_
#undef W2S_
}

// ---------------- launcher ----------------
extern "C" void kernel_launch(void* const* d_in, const int* in_sizes, int n_in,
                              void* d_out, int out_size)
{
    const float* features   = (const float*)d_in[0];
    const float* slots_init = (const float*)d_in[1];
    const float* g_feat     = (const float*)d_in[2];
    const float* b_feat     = (const float*)d_in[3];
    const float* g_slots    = (const float*)d_in[4];
    const float* b_slots    = (const float*)d_in[5];
    const float* g_mlp      = (const float*)d_in[6];
    const float* b_mlp      = (const float*)d_in[7];
    const float* Wk         = (const float*)d_in[8];
    const float* Wv         = (const float*)d_in[9];
    const float* Wq         = (const float*)d_in[10];
    const float* w_ih       = (const float*)d_in[11];
    const float* w_hh       = (const float*)d_in[12];
    const float* b_ih       = (const float*)d_in[13];
    const float* b_hh       = (const float*)d_in[14];
    const float* W1         = (const float*)d_in[15];
    const float* b1         = (const float*)d_in[16];
    const float* W2         = (const float*)d_in[17];
    const float* b2         = (const float*)d_in[18];

    float* out       = (float*)d_out;
    float* out_slots = out;                         // [64,8,256]
    float* out_attn  = out + (size_t)64 * 8 * 256;  // [64,8,4096]

    float *S0, *S1, *qkbuf, *U, *rowsum, *gh;
    float *Wqk, *Bcat, *c1cat, *c2cat, *W1g, *c1m, *c2m, *Wvih;
    cudaGetSymbolAddress((void**)&S0, g_S0);
    cudaGetSymbolAddress((void**)&S1, g_S1);
    cudaGetSymbolAddress((void**)&qkbuf, g_qkbuf);
    cudaGetSymbolAddress((void**)&U, g_Ubuf);
    cudaGetSymbolAddress((void**)&rowsum, g_rowsum);
    cudaGetSymbolAddress((void**)&gh, g_gh);
    cudaGetSymbolAddress((void**)&Wqk, g_Wqk);
    cudaGetSymbolAddress((void**)&Bcat, g_Bcat);
    cudaGetSymbolAddress((void**)&c1cat, g_c1cat);
    cudaGetSymbolAddress((void**)&c2cat, g_c2cat);
    cudaGetSymbolAddress((void**)&W1g, g_W1g);
    cudaGetSymbolAddress((void**)&c1m, g_c1m);
    cudaGetSymbolAddress((void**)&c2m, g_c2m);
    cudaGetSymbolAddress((void**)&Wvih, g_Wvih);

    // ---- precompute (3 nodes) ----
    gemm_tn_k<<<dim3(4, 4), 256>>>(Wq, Wk, Wqk, 256, 256, 256);
    build_misc_k<<<339, 256>>>(Wqk, g_slots, b_slots, w_hh, b_hh,
                               W1, g_mlp, b_mlp, b1,
                               Bcat, c1cat, c2cat, W1g, c1m, c2m);
    gemm2_k<0><<<dim3(12, 4), 256>>>(w_ih, Wv, Wvih, 256, nullptr, 0, 1 << 30,
                                     256, 256, 256, 0,
                                     nullptr, nullptr, 0, nullptr, nullptr, 0, 0,
                                     nullptr, nullptr);

    cudaMemcpyAsync(S1, slots_init, (size_t)512 * 256 * 4,
                    cudaMemcpyDeviceToDevice, 0);

    for (int it = 0; it < kNITER; it++) {
        // [qk | gh] = LN(S1)@Wqk | S1@w_hh^T + b_hh; side job: zero U/rowsum
        gemm2_k<1><<<dim3(8, 16), 256>>>(S1, Bcat, qkbuf, 256, gh, 768, 256,
                                         1024, 256, 256, 0,
                                         c1cat, c2cat, 256, nullptr, nullptr, 0, 0,
                                         U, rowsum);
        attn_fused_k<<<dim3(32, 64), 256>>>(features, qkbuf, g_feat, b_feat,
                                            out_attn, U, rowsum);
        // gates + GRU fused; h = S1, writes S0 & S1
        gru_gemm_k<<<dim3(8, 4), 256>>>(U, Wvih, rowsum, b_ih, gh, S0, S1);
        // MLP fused: reads S0, atomically accumulates into S1
        mlp_k<<<dim3(8, 16), 256>>>(S0, W1g, c1m, c2m, W2, b2, S1);
    }
    cudaMemcpyAsync(out_slots, S1, (size_t)512 * 256 * 4,
                    cudaMemcpyDeviceToDevice, 0);
}